// round 11
// baseline (speedup 1.0000x reference)
#include <cuda_runtime.h>
#include <cuda_bf16.h>
#include <cuda_fp16.h>
#include <cuda_fp8.h>
#include <cstdint>

#define L 2048
#define HID 4096
#define NH 32
#define NKV 8
#define HD 128
#define MAXP 4096

// ---------------------------------------------------------------------------
// PTX helpers (sm_80/89-class instructions: valid on baseline sm_103 target)
// ---------------------------------------------------------------------------
__device__ __forceinline__ uint32_t smem_u32(const void* p) {
    uint32_t a;
    asm("{ .reg .u64 t; cvta.to.shared.u64 t, %1; cvt.u32.u64 %0, t; }" : "=r"(a) : "l"(p));
    return a;
}
__device__ __forceinline__ float fast_exp2(float x) {
    float y;
    asm("ex2.approx.f32 %0, %1;" : "=f"(y) : "f"(x));
    return y;
}
#define LDSM_X4(r0, r1, r2, r3, addr)                                              \
    asm volatile("ldmatrix.sync.aligned.m8n8.x4.shared.b16 {%0,%1,%2,%3}, [%4];"   \
                 : "=r"(r0), "=r"(r1), "=r"(r2), "=r"(r3) : "r"(addr))
#define LDSM_X4_T(r0, r1, r2, r3, addr)                                            \
    asm volatile("ldmatrix.sync.aligned.m8n8.x4.trans.shared.b16 {%0,%1,%2,%3}, [%4];" \
                 : "=r"(r0), "=r"(r1), "=r"(r2), "=r"(r3) : "r"(addr))
#define MMA_BF16(d, a, b)                                                          \
    asm volatile("mma.sync.aligned.m16n8k16.row.col.f32.bf16.bf16.f32 "            \
                 "{%0,%1,%2,%3}, {%4,%5,%6,%7}, {%8,%9}, {%0,%1,%2,%3};"           \
                 : "+f"((d)[0]), "+f"((d)[1]), "+f"((d)[2]), "+f"((d)[3])          \
                 : "r"((a)[0]), "r"((a)[1]), "r"((a)[2]), "r"((a)[3]),             \
                   "r"((b)[0]), "r"((b)[1]))
#define MMA_F16(d, a, b)                                                           \
    asm volatile("mma.sync.aligned.m16n8k16.row.col.f32.f16.f16.f32 "              \
                 "{%0,%1,%2,%3}, {%4,%5,%6,%7}, {%8,%9}, {%0,%1,%2,%3};"           \
                 : "+f"((d)[0]), "+f"((d)[1]), "+f"((d)[2]), "+f"((d)[3])          \
                 : "r"((a)[0]), "r"((a)[1]), "r"((a)[2]), "r"((a)[3]),             \
                   "r"((b)[0]), "r"((b)[1]))
#define MMA_FP8(d, a, b)                                                           \
    asm volatile("mma.sync.aligned.m16n8k32.row.col.f32.e4m3.e4m3.f32 "            \
                 "{%0,%1,%2,%3}, {%4,%5,%6,%7}, {%8,%9}, {%0,%1,%2,%3};"           \
                 : "+f"((d)[0]), "+f"((d)[1]), "+f"((d)[2]), "+f"((d)[3])          \
                 : "r"((a)[0]), "r"((a)[1]), "r"((a)[2]), "r"((a)[3]),             \
                   "r"((b)[0]), "r"((b)[1]))
#define CP_ASYNC16(dst, src)                                                       \
    asm volatile("cp.async.cg.shared.global [%0], [%1], 16;" :: "r"(dst), "l"(src))
#define CP_COMMIT() asm volatile("cp.async.commit_group;" ::: "memory")
#define CP_WAIT(n) asm volatile("cp.async.wait_group %0;" :: "n"(n) : "memory")

// scales for the fp8 correction path (activation hi x16, resid x2^16;
// weight hi x128, resid x2^19; both cross products share scale 2^23)
#define SA1 16.0f
#define SA2 65536.0f
#define SB1 128.0f
#define SB2 524288.0f
#define INV_CORR (1.0f / 8388608.0f)

__device__ __forceinline__ uint8_t to_e4m3(float x) {
    return (uint8_t)__nv_cvt_float_to_fp8(x, __NV_SATFINITE, __NV_E4M3);
}

// ---------------------------------------------------------------------------
// scratch (device globals; no runtime alloc)
// ---------------------------------------------------------------------------
#define NW_TOTAL 41943040
#define OFF_WQ 0
#define OFF_WK 16777216
#define OFF_WV 20971520
#define OFF_WO 25165824

// GEMM operands: fp16 main + e4m3 hi/lo correction forms
__device__ __half  g_hf[(size_t)L * HID];
__device__ uint8_t g_h8a[(size_t)L * HID];
__device__ uint8_t g_h8b[(size_t)L * HID];
__device__ __half  g_wf[(size_t)NW_TOTAL];
__device__ uint8_t g_w8a[(size_t)NW_TOTAL];
__device__ uint8_t g_w8b[(size_t)NW_TOTAL];
__device__ __half  g_af[(size_t)L * HID];
__device__ uint8_t g_a8a[(size_t)L * HID];
__device__ uint8_t g_a8b[(size_t)L * HID];
// flash operands (bf16 3-term path, unchanged this round)
__device__ __nv_bfloat16 g_qh[(size_t)L * HID];
__device__ __nv_bfloat16 g_ql[(size_t)L * HID];
__device__ __nv_bfloat16 g_kh[(size_t)L * NKV * HD];
__device__ __nv_bfloat16 g_kl[(size_t)L * NKV * HD];
__device__ __nv_bfloat16 g_vb[(size_t)L * NKV * HD];
__device__ float g_q[(size_t)L * HID];
__device__ float g_k[(size_t)L * NKV * HD];
__device__ float g_v[(size_t)L * NKV * HD];

__device__ __forceinline__ void split_bf16(float x, __nv_bfloat16& hi, __nv_bfloat16& lo) {
    hi = __float2bfloat16_rn(x);
    lo = __float2bfloat16_rn(x - __bfloat162float(hi));
}
__device__ __forceinline__ uint32_t pack_bf16(float lo, float hi) {
    __nv_bfloat162 t = __floats2bfloat162_rn(lo, hi);
    return *(uint32_t*)&t;
}

// ---------------------------------------------------------------------------
// cache copy — rows [L, MAXP) only (rope_kv fully writes rows [0, L))
// ---------------------------------------------------------------------------
__global__ void copy_caches_kernel(const float4* __restrict__ kin,
                                   const float4* __restrict__ vin,
                                   float4* __restrict__ kout,
                                   float4* __restrict__ vout) {
    int idx = blockIdx.x * 256 + threadIdx.x;
    const int n4 = (MAXP - L) * NKV * HD / 4;
    const int off = L * NKV * HD / 4;
    if (idx < n4) kout[off + idx] = kin[off + idx];
    else vout[off + idx - n4] = vin[off + idx - n4];
}

// ---------------------------------------------------------------------------
// fused weight convert: fp32 -> fp16 + e4m3 hi (x128) + e4m3 resid (x2^19)
// ---------------------------------------------------------------------------
__global__ void convert_all_kernel(const float4* __restrict__ wq,
                                   const float4* __restrict__ wk,
                                   const float4* __restrict__ wv,
                                   const float4* __restrict__ wo,
                                   __half* __restrict__ wf,
                                   uint8_t* __restrict__ w8a,
                                   uint8_t* __restrict__ w8b) {
    int i = blockIdx.x * 256 + threadIdx.x;  // [0, NW_TOTAL/4)
    const float4* src;
    int base;
    if (i < OFF_WK / 4) { src = wq; base = 0; }
    else if (i < OFF_WV / 4) { src = wk; base = OFF_WK / 4; }
    else if (i < OFF_WO / 4) { src = wv; base = OFF_WV / 4; }
    else { src = wo; base = OFF_WO / 4; }
    float4 v = src[i - base];
    float f[4] = {v.x, v.y, v.z, v.w};
    __half h[4];
    uint32_t pa = 0, pb = 0;
#pragma unroll
    for (int j = 0; j < 4; ++j) {
        h[j] = __float2half_rn(f[j]);
        float r = f[j] - __half2float(h[j]);
        pa |= (uint32_t)to_e4m3(f[j] * SB1) << (8 * j);
        pb |= (uint32_t)to_e4m3(r * SB2) << (8 * j);
    }
    __half2* hp = (__half2*)(wf + (size_t)i * 4);
    hp[0] = __halves2half2(h[0], h[1]);
    hp[1] = __halves2half2(h[2], h[3]);
    *(uint32_t*)(w8a + (size_t)i * 4) = pa;
    *(uint32_t*)(w8b + (size_t)i * 4) = pb;
}

// ---------------------------------------------------------------------------
// RMSNorm -> fp16 + e4m3 forms
// ---------------------------------------------------------------------------
__global__ void __launch_bounds__(256) rmsnorm_kernel(const float* __restrict__ x,
                                                      const float* __restrict__ w) {
    int row = blockIdx.x;
    const float* xr = x + (size_t)row * HID;
    int t = threadIdx.x;
    float vals[16];
    float local = 0.f;
#pragma unroll
    for (int i = 0; i < 16; ++i) {
        float v = xr[t + i * 256];
        vals[i] = v;
        local += v * v;
    }
    __shared__ float red[8];
#pragma unroll
    for (int o = 16; o; o >>= 1) local += __shfl_xor_sync(0xffffffffu, local, o);
    if ((t & 31) == 0) red[t >> 5] = local;
    __syncthreads();
    if (t < 8) {
        float v = red[t];
#pragma unroll
        for (int o = 4; o; o >>= 1) v += __shfl_xor_sync(0xffu, v, o);
        if (t == 0) red[0] = v;
    }
    __syncthreads();
    float rms = rsqrtf(red[0] / (float)HID + 1e-5f);
    size_t base = (size_t)row * HID;
#pragma unroll
    for (int i = 0; i < 16; ++i) {
        float y = vals[i] * rms * w[t + i * 256];
        __half hf = __float2half_rn(y);
        float r = y - __half2float(hf);
        size_t idx = base + t + i * 256;
        g_hf[idx] = hf;
        g_h8a[idx] = to_e4m3(y * SA1);
        g_h8b[idx] = to_e4m3(r * SA2);
    }
}

// ---------------------------------------------------------------------------
// GEMM: fp16 main MMA + e4m3 k32 correction MMA (2 instruction-units vs 3).
// CTA 128x128, 256 thr (8 warps 2x4), warp tile 64x32, K-chunk 64, 2-stage.
// MODE 1: fused QKV (N=6144; route q/k/v).  MODE 2: +res.
// ---------------------------------------------------------------------------
#define AF_OFF 0
#define A8A_OFF 18432
#define A8B_OFF 28672
#define BF_OFF 38912
#define B8A_OFF 57344
#define B8B_OFF 67584
#define GSTAGE 77824
#define GEMM_SMEM (2 * GSTAGE)   // 155648

template <int MODE>
__global__ void __launch_bounds__(256, 1) mma_gemm_kernel(
    const __half* __restrict__ Af, const uint8_t* __restrict__ A8a,
    const uint8_t* __restrict__ A8b,
    const __half* __restrict__ Bf, const uint8_t* __restrict__ B8a,
    const uint8_t* __restrict__ B8b,
    float* __restrict__ C, float* __restrict__ Ck, float* __restrict__ Cvv,
    int N, const float* __restrict__ res) {
    extern __shared__ char sm[];
    const uint32_t sb = smem_u32(sm);
    const int tid = threadIdx.x;
    const int lane = tid & 31, w = tid >> 5;
    const int wm = w >> 2, wn = w & 3;      // warp tile 64x32
    const int bm = blockIdx.y * 128, bn = blockIdx.x * 128;

    float acc[4][4][4], cacc[4][4][4];
#pragma unroll
    for (int a = 0; a < 4; ++a)
#pragma unroll
        for (int b = 0; b < 4; ++b)
#pragma unroll
            for (int c = 0; c < 4; ++c) { acc[a][b][c] = 0.f; cacc[a][b][c] = 0.f; }

    auto issue = [&](int c, int s) {
        const uint32_t st = sb + s * GSTAGE;
        // fp16 A: 128x64 halfs = 16KB -> 1024 cp
#pragma unroll
        for (int j = 0; j < 4; ++j) {
            const int local = tid + j * 256;
            const int row = local >> 3, seg = local & 7;
            CP_ASYNC16(st + AF_OFF + row * 144 + seg * 16,
                       Af + (size_t)(bm + row) * HID + c * 64 + seg * 8);
        }
        // fp16 B
#pragma unroll
        for (int j = 0; j < 4; ++j) {
            const int local = tid + j * 256;
            const int row = local >> 3, seg = local & 7;
            CP_ASYNC16(st + BF_OFF + row * 144 + seg * 16,
                       Bf + (size_t)(bn + row) * HID + c * 64 + seg * 8);
        }
        // fp8 tiles: 128x64 bytes = 8KB each -> 512 cp each
#pragma unroll
        for (int j = 0; j < 2; ++j) {
            const int local = tid + j * 256;
            const int row = local >> 2, seg = local & 3;
            CP_ASYNC16(st + A8A_OFF + row * 80 + seg * 16,
                       A8a + (size_t)(bm + row) * HID + c * 64 + seg * 16);
        }
#pragma unroll
        for (int j = 0; j < 2; ++j) {
            const int local = tid + j * 256;
            const int row = local >> 2, seg = local & 3;
            CP_ASYNC16(st + A8B_OFF + row * 80 + seg * 16,
                       A8b + (size_t)(bm + row) * HID + c * 64 + seg * 16);
        }
#pragma unroll
        for (int j = 0; j < 2; ++j) {
            const int local = tid + j * 256;
            const int row = local >> 2, seg = local & 3;
            CP_ASYNC16(st + B8A_OFF + row * 80 + seg * 16,
                       B8a + (size_t)(bn + row) * HID + c * 64 + seg * 16);
        }
#pragma unroll
        for (int j = 0; j < 2; ++j) {
            const int local = tid + j * 256;
            const int row = local >> 2, seg = local & 3;
            CP_ASYNC16(st + B8B_OFF + row * 80 + seg * 16,
                       B8b + (size_t)(bn + row) * HID + c * 64 + seg * 16);
        }
    };

    auto compute = [&](int s) {
        const uint32_t base = sb + s * GSTAGE;
        const int rsel = lane & 15;
        const int csel = (lane >> 4) << 4;
        // ---- fp16 main: 4 k16 steps ----
#pragma unroll
        for (int ks = 0; ks < 4; ++ks) {
            uint32_t a[4][4];
#pragma unroll
            for (int mt = 0; mt < 4; ++mt) {
                uint32_t ad = base + AF_OFF + (wm * 64 + mt * 16 + rsel) * 144 + ks * 32 + csel;
                LDSM_X4(a[mt][0], a[mt][1], a[mt][2], a[mt][3], ad);
            }
            uint32_t b[4][2];
#pragma unroll
            for (int g = 0; g < 2; ++g) {
                uint32_t bd = base + BF_OFF + (wn * 32 + g * 16 + rsel) * 144 + ks * 32 + csel;
                uint32_t t0, t1, t2, t3;
                LDSM_X4(t0, t1, t2, t3, bd);
                b[2 * g][0] = t0; b[2 * g][1] = t2;
                b[2 * g + 1][0] = t1; b[2 * g + 1][1] = t3;
            }
#pragma unroll
            for (int nt = 0; nt < 4; ++nt)
#pragma unroll
                for (int mt = 0; mt < 4; ++mt)
                    MMA_F16(acc[mt][nt], a[mt], b[nt]);
        }
        // ---- fp8 correction: 2 k32 steps: A8a*B8b + A8b*B8a ----
#pragma unroll
        for (int ks = 0; ks < 2; ++ks) {
            uint32_t aa[4][4], ab[4][4];
#pragma unroll
            for (int mt = 0; mt < 4; ++mt) {
                uint32_t ad = base + A8A_OFF + (wm * 64 + mt * 16 + rsel) * 80 + ks * 32 + csel;
                LDSM_X4(aa[mt][0], aa[mt][1], aa[mt][2], aa[mt][3], ad);
                uint32_t ad2 = base + A8B_OFF + (wm * 64 + mt * 16 + rsel) * 80 + ks * 32 + csel;
                LDSM_X4(ab[mt][0], ab[mt][1], ab[mt][2], ab[mt][3], ad2);
            }
            uint32_t bl[4][2], bh[4][2];
#pragma unroll
            for (int g = 0; g < 2; ++g) {
                uint32_t bd = base + B8B_OFF + (wn * 32 + g * 16 + rsel) * 80 + ks * 32 + csel;
                uint32_t t0, t1, t2, t3;
                LDSM_X4(t0, t1, t2, t3, bd);
                bl[2 * g][0] = t0; bl[2 * g][1] = t2;
                bl[2 * g + 1][0] = t1; bl[2 * g + 1][1] = t3;
                uint32_t bd2 = base + B8A_OFF + (wn * 32 + g * 16 + rsel) * 80 + ks * 32 + csel;
                LDSM_X4(t0, t1, t2, t3, bd2);
                bh[2 * g][0] = t0; bh[2 * g][1] = t2;
                bh[2 * g + 1][0] = t1; bh[2 * g + 1][1] = t3;
            }
#pragma unroll
            for (int nt = 0; nt < 4; ++nt)
#pragma unroll
                for (int mt = 0; mt < 4; ++mt)
                    MMA_FP8(cacc[mt][nt], aa[mt], bl[nt]);
#pragma unroll
            for (int nt = 0; nt < 4; ++nt)
#pragma unroll
                for (int mt = 0; mt < 4; ++mt)
                    MMA_FP8(cacc[mt][nt], ab[mt], bh[nt]);
        }
    };

    issue(0, 0); CP_COMMIT();
    issue(1, 1); CP_COMMIT();
#pragma unroll 1
    for (int c = 0; c < 64; ++c) {
        if (c + 1 < 64) { CP_WAIT(1); } else { CP_WAIT(0); }
        __syncthreads();
        compute(c & 1);
        if (c + 2 < 64) {
            __syncthreads();
            issue(c + 2, c & 1);
            CP_COMMIT();
        }
    }

    // epilogue: D = main + corr * 2^-23; route output
    float* Cout = C;
    int ncols = N, bnl = bn;
    if (MODE == 1) {
        if (bn < 4096) { Cout = C; ncols = 4096; bnl = bn; }
        else if (bn < 5120) { Cout = Ck; ncols = 1024; bnl = bn - 4096; }
        else { Cout = Cvv; ncols = 1024; bnl = bn - 5120; }
    }
#pragma unroll
    for (int mt = 0; mt < 4; ++mt)
#pragma unroll
        for (int nt = 0; nt < 4; ++nt) {
            int row = bm + wm * 64 + mt * 16 + (lane >> 2);
            int col = bnl + wn * 32 + nt * 8 + ((lane & 3) << 1);
            size_t o0 = (size_t)row * ncols + col;
            size_t o1 = (size_t)(row + 8) * ncols + col;
            float2 v0 = make_float2(acc[mt][nt][0] + cacc[mt][nt][0] * INV_CORR,
                                    acc[mt][nt][1] + cacc[mt][nt][1] * INV_CORR);
            float2 v1 = make_float2(acc[mt][nt][2] + cacc[mt][nt][2] * INV_CORR,
                                    acc[mt][nt][3] + cacc[mt][nt][3] * INV_CORR);
            if (MODE == 2) {
                float2 r0 = *(const float2*)&res[o0];
                float2 r1 = *(const float2*)&res[o1];
                v0.x += r0.x; v0.y += r0.y;
                v1.x += r1.x; v1.y += r1.y;
            }
            *(float2*)&Cout[o0] = v0;
            *(float2*)&Cout[o1] = v1;
        }
}

// ---------------------------------------------------------------------------
// RoPE Q: fp32 in g_q -> scaled (1/sqrt(hd) * log2e) split bf16 (flash input)
// ---------------------------------------------------------------------------
__global__ void rope_q_kernel(const float* __restrict__ cosb, const float* __restrict__ sinb) {
    const float QS = 0.08838834764831845f * 1.4426950408889634f;
    int idx = blockIdx.x * 256 + threadIdx.x;
    int d = idx & 63;
    int h = (idx >> 6) & (NH - 1);
    int i = idx >> 11;
    const float* qp = g_q + (size_t)i * HID + h * HD;
    float c0 = cosb[i * HD + d], s0 = sinb[i * HD + d];
    float c1 = cosb[i * HD + d + 64], s1 = sinb[i * HD + d + 64];
    float q0 = qp[d], q1 = qp[d + 64];
    float r0 = (q0 * c0 - q1 * s0) * QS;
    float r1 = (q1 * c1 + q0 * s1) * QS;
    size_t base = (size_t)i * HID + h * HD;
    __nv_bfloat16 hh, ll;
    split_bf16(r0, hh, ll);
    g_qh[base + d] = hh; g_ql[base + d] = ll;
    split_bf16(r1, hh, ll);
    g_qh[base + d + 64] = hh; g_ql[base + d + 64] = ll;
}

__global__ void rope_kv_kernel(const float* __restrict__ cosb, const float* __restrict__ sinb,
                               float* __restrict__ kc_out, float* __restrict__ vc_out) {
    int idx = blockIdx.x * 256 + threadIdx.x;
    int d = idx & 63;
    int h = (idx >> 6) & (NKV - 1);
    int i = idx >> 9;
    size_t base = (size_t)i * (NKV * HD) + h * HD;
    float c0 = cosb[i * HD + d], s0 = sinb[i * HD + d];
    float c1 = cosb[i * HD + d + 64], s1 = sinb[i * HD + d + 64];
    float k0 = g_k[base + d], k1 = g_k[base + d + 64];
    float k0n = k0 * c0 - k1 * s0;
    float k1n = k1 * c1 + k0 * s1;
    kc_out[base + d] = k0n;
    kc_out[base + d + 64] = k1n;
    __nv_bfloat16 hh, ll;
    split_bf16(k0n, hh, ll);
    g_kh[base + d] = hh; g_kl[base + d] = ll;
    split_bf16(k1n, hh, ll);
    g_kh[base + d + 64] = hh; g_kl[base + d + 64] = ll;
    float v0 = g_v[base + d], v1 = g_v[base + d + 64];
    vc_out[base + d] = v0;
    vc_out[base + d + 64] = v1;
    g_vb[base + d] = __float2bfloat16_rn(v0);
    g_vb[base + d + 64] = __float2bfloat16_rn(v1);
}

// ---------------------------------------------------------------------------
// Flash attention (unchanged bf16 3-term QK^T; epilogue emits fp16+fp8 forms)
// ---------------------------------------------------------------------------
#define FSTRIDE 272
#define FQH 0
#define FQL 34816
#define FKH 69632
#define FKL 87040
#define FV 104448
#define FLASH_SMEM 121856

__global__ void __launch_bounds__(256, 1) flash_kernel() {
    extern __shared__ char sm[];
    const uint32_t sb = smem_u32(sm);
    const int tid = threadIdx.x;
    const int lane = tid & 31, w = tid >> 5;
    const int qt = gridDim.x - 1 - blockIdx.x;
    const int head = blockIdx.y;
    const int kvh = head >> 2;
    const int rsel = lane & 15;
    const int csel = (lane >> 4) << 4;

#pragma unroll
    for (int j = 0; j < 16; ++j) {
        const int term = j >> 3;
        const int local = tid + (j & 7) * 256;
        const int row = local >> 4;
        const int seg = local & 15;
        const __nv_bfloat16* src = (term ? g_ql : g_qh);
        const void* g = src + (size_t)(qt * 128 + row) * HID + head * HD + seg * 8;
        uint32_t dst = sb + (term ? FQL : FQH) + row * FSTRIDE + seg * 16;
        CP_ASYNC16(dst, g);
    }
    CP_COMMIT();

    float o_[16][4];
#pragma unroll
    for (int n = 0; n < 16; ++n)
#pragma unroll
        for (int c = 0; c < 4; ++c) o_[n][c] = 0.f;
    float m_[2] = {-1e30f, -1e30f};
    float l_[2] = {0.f, 0.f};

    const int kt_end = 2 * qt + 2;
#pragma unroll 1
    for (int kt = 0; kt < kt_end; ++kt) {
        __syncthreads();
#pragma unroll
        for (int j = 0; j < 8; ++j) {
            const int t = j >> 2;
            const int local = tid + (j & 3) * 256;
            const int row = local >> 4;
            const int seg = local & 15;
            const __nv_bfloat16* src = (t == 0) ? g_kh : g_kl;
            const void* g = src + (size_t)(kt * 64 + row) * (NKV * HD) + kvh * HD + seg * 8;
            uint32_t dst = sb + ((t == 0) ? FKH : FKL) + row * FSTRIDE + seg * 16;
            CP_ASYNC16(dst, g);
        }
        CP_COMMIT();
#pragma unroll
        for (int j = 0; j < 4; ++j) {
            const int local = tid + j * 256;
            const int row = local >> 4;
            const int seg = local & 15;
            const void* g = g_vb + (size_t)(kt * 64 + row) * (NKV * HD) + kvh * HD + seg * 8;
            uint32_t dst = sb + FV + row * FSTRIDE + seg * 16;
            CP_ASYNC16(dst, g);
        }
        CP_COMMIT();

        CP_WAIT(1);
        __syncthreads();

        float s[8][4];
#pragma unroll
        for (int n = 0; n < 8; ++n)
#pragma unroll
            for (int c = 0; c < 4; ++c) s[n][c] = 0.f;
#pragma unroll
        for (int ks = 0; ks < 8; ++ks) {
            uint32_t ah[4], al[4];
            uint32_t aaddr = sb + FQH + (w * 16 + rsel) * FSTRIDE + ks * 32 + csel;
            LDSM_X4(ah[0], ah[1], ah[2], ah[3], aaddr);
            LDSM_X4(al[0], al[1], al[2], al[3], aaddr + (FQL - FQH));
#pragma unroll
            for (int half = 0; half < 2; ++half) {
                uint32_t bh[4][2], bl[4][2];
#pragma unroll
                for (int g = 0; g < 2; ++g) {
                    uint32_t bd = sb + FKH +
                                  ((half * 2 + g) * 16 + rsel) * FSTRIDE + ks * 32 + csel;
                    uint32_t t0, t1, t2, t3;
                    LDSM_X4(t0, t1, t2, t3, bd);
                    bh[2 * g][0] = t0; bh[2 * g][1] = t2;
                    bh[2 * g + 1][0] = t1; bh[2 * g + 1][1] = t3;
                    LDSM_X4(t0, t1, t2, t3, bd + (FKL - FKH));
                    bl[2 * g][0] = t0; bl[2 * g][1] = t2;
                    bl[2 * g + 1][0] = t1; bl[2 * g + 1][1] = t3;
                }
#pragma unroll
                for (int n = 0; n < 4; ++n) MMA_BF16(s[half * 4 + n], ah, bh[n]);
#pragma unroll
                for (int n = 0; n < 4; ++n) MMA_BF16(s[half * 4 + n], ah, bl[n]);
#pragma unroll
                for (int n = 0; n < 4; ++n) MMA_BF16(s[half * 4 + n], al, bh[n]);
            }
        }

        if (kt >= 2 * qt) {
            const int r0g = qt * 128 + w * 16 + (lane >> 2);
#pragma unroll
            for (int j = 0; j < 8; ++j) {
                int cb = kt * 64 + j * 8 + ((lane & 3) << 1);
                if (cb > r0g) s[j][0] = -1e30f;
                if (cb + 1 > r0g) s[j][1] = -1e30f;
                if (cb > r0g + 8) s[j][2] = -1e30f;
                if (cb + 1 > r0g + 8) s[j][3] = -1e30f;
            }
        }

#pragma unroll
        for (int i = 0; i < 2; ++i) {
            float mt_ = -1e30f;
#pragma unroll
            for (int j = 0; j < 8; ++j)
                mt_ = fmaxf(mt_, fmaxf(s[j][2 * i], s[j][2 * i + 1]));
            mt_ = fmaxf(mt_, __shfl_xor_sync(0xffffffffu, mt_, 1));
            mt_ = fmaxf(mt_, __shfl_xor_sync(0xffffffffu, mt_, 2));
            float mn = fmaxf(m_[i], mt_);
            float corr = fast_exp2(m_[i] - mn);
            m_[i] = mn;
            float rs = 0.f;
#pragma unroll
            for (int j = 0; j < 8; ++j) {
                float p0 = fast_exp2(s[j][2 * i] - mn);
                float p1 = fast_exp2(s[j][2 * i + 1] - mn);
                s[j][2 * i] = p0;
                s[j][2 * i + 1] = p1;
                rs += p0 + p1;
            }
            rs += __shfl_xor_sync(0xffffffffu, rs, 1);
            rs += __shfl_xor_sync(0xffffffffu, rs, 2);
            l_[i] = l_[i] * corr + rs;
#pragma unroll
            for (int n = 0; n < 16; ++n) {
                o_[n][2 * i] *= corr;
                o_[n][2 * i + 1] *= corr;
            }
        }

        uint32_t pa[4][4];
#pragma unroll
        for (int t = 0; t < 4; ++t) {
            pa[t][0] = pack_bf16(s[2 * t][0], s[2 * t][1]);
            pa[t][1] = pack_bf16(s[2 * t][2], s[2 * t][3]);
            pa[t][2] = pack_bf16(s[2 * t + 1][0], s[2 * t + 1][1]);
            pa[t][3] = pack_bf16(s[2 * t + 1][2], s[2 * t + 1][3]);
        }

        CP_WAIT(0);
        __syncthreads();

#pragma unroll
        for (int t = 0; t < 4; ++t) {
#pragma unroll
            for (int g = 0; g < 8; ++g) {
                uint32_t vaddr = sb + FV + (t * 16 + rsel) * FSTRIDE +
                                 (g * 16 + ((lane >> 4) << 3)) * 2;
                uint32_t t0, t1, t2, t3;
                LDSM_X4_T(t0, t1, t2, t3, vaddr);
                uint32_t b0[2] = {t0, t1}, b1[2] = {t2, t3};
                MMA_BF16(o_[2 * g], pa[t], b0);
                MMA_BF16(o_[2 * g + 1], pa[t], b1);
            }
        }
    }

    // epilogue: fp16 + e4m3 forms for the O projection
    const float inv0 = 1.f / l_[0];
    const float inv1 = 1.f / l_[1];
    const int r0g = qt * 128 + w * 16 + (lane >> 2);
#pragma unroll
    for (int nt = 0; nt < 16; ++nt) {
        int col = head * HD + nt * 8 + ((lane & 3) << 1);
        size_t o0 = (size_t)r0g * HID + col;
        size_t o1 = o0 + (size_t)8 * HID;
#pragma unroll
        for (int half = 0; half < 2; ++half) {
            size_t oo = half ? o1 : o0;
            float y0 = o_[nt][2 * half + 0] * (half ? inv1 : inv0);
            float y1 = o_[nt][2 * half + 1] * (half ? inv1 : inv0);
            __half h0 = __float2half_rn(y0), h1 = __float2half_rn(y1);
            float r0f = y0 - __half2float(h0), r1f = y1 - __half2float(h1);
            *(__half2*)(g_af + oo) = __halves2half2(h0, h1);
            uint16_t p8a = (uint16_t)to_e4m3(y0 * SA1) |
                           ((uint16_t)to_e4m3(y1 * SA1) << 8);
            uint16_t p8b = (uint16_t)to_e4m3(r0f * SA2) |
                           ((uint16_t)to_e4m3(r1f * SA2) << 8);
            *(uint16_t*)(g_a8a + oo) = p8a;
            *(uint16_t*)(g_a8b + oo) = p8b;
        }
    }
}

// ---------------------------------------------------------------------------
// launch
// ---------------------------------------------------------------------------
extern "C" void kernel_launch(void* const* d_in, const int* in_sizes, int n_in,
                              void* d_out, int out_size) {
    const float* x = (const float*)d_in[0];
    const float* cosb = (const float*)d_in[1];
    const float* sinb = (const float*)d_in[2];
    // d_in[3] position_ids (arange; not dereferenced), d_in[4] seq_len
    const float* kc_in = (const float*)d_in[5];
    const float* vc_in = (const float*)d_in[6];
    const float* lnw = (const float*)d_in[7];
    const float* Wq = (const float*)d_in[8];
    const float* Wk = (const float*)d_in[9];
    const float* Wv = (const float*)d_in[10];
    const float* Wo = (const float*)d_in[11];

    float* out = (float*)d_out;
    float* kc_out = out + (size_t)L * HID;
    float* vc_out = kc_out + (size_t)MAXP * NKV * HD;

    __half *pHf, *pWf, *pAf;
    uint8_t *pH8a, *pH8b, *pW8a, *pW8b, *pA8a, *pA8b;
    float *pQ, *pK, *pV;
    cudaGetSymbolAddress((void**)&pHf, g_hf);
    cudaGetSymbolAddress((void**)&pH8a, g_h8a);
    cudaGetSymbolAddress((void**)&pH8b, g_h8b);
    cudaGetSymbolAddress((void**)&pWf, g_wf);
    cudaGetSymbolAddress((void**)&pW8a, g_w8a);
    cudaGetSymbolAddress((void**)&pW8b, g_w8b);
    cudaGetSymbolAddress((void**)&pAf, g_af);
    cudaGetSymbolAddress((void**)&pA8a, g_a8a);
    cudaGetSymbolAddress((void**)&pA8b, g_a8b);
    cudaGetSymbolAddress((void**)&pQ, g_q);
    cudaGetSymbolAddress((void**)&pK, g_k);
    cudaGetSymbolAddress((void**)&pV, g_v);

    copy_caches_kernel<<<(2 * (MAXP - L) * NKV * HD / 4) / 256, 256>>>(
        (const float4*)kc_in, (const float4*)vc_in, (float4*)kc_out, (float4*)vc_out);

    convert_all_kernel<<<(NW_TOTAL / 4) / 256, 256>>>(
        (const float4*)Wq, (const float4*)Wk, (const float4*)Wv, (const float4*)Wo,
        pWf, pW8a, pW8b);

    rmsnorm_kernel<<<L, 256>>>(x, lnw);

    cudaFuncSetAttribute((const void*)mma_gemm_kernel<1>,
                         cudaFuncAttributeMaxDynamicSharedMemorySize, GEMM_SMEM);
    cudaFuncSetAttribute((const void*)mma_gemm_kernel<2>,
                         cudaFuncAttributeMaxDynamicSharedMemorySize, GEMM_SMEM);

    // fused Q+K+V projection: N = 6144, grid (48, 16)
    mma_gemm_kernel<1><<<dim3(6144 / 128, L / 128), 256, GEMM_SMEM>>>(
        pHf, pH8a, pH8b, pWf, pW8a, pW8b, pQ, pK, pV, 6144, nullptr);

    rope_q_kernel<<<(L * NH * 64) / 256, 256>>>(cosb, sinb);
    rope_kv_kernel<<<(L * NKV * 64) / 256, 256>>>(cosb, sinb, kc_out, vc_out);

    cudaFuncSetAttribute(flash_kernel, cudaFuncAttributeMaxDynamicSharedMemorySize, FLASH_SMEM);
    flash_kernel<<<dim3(L / 128, NH), 256, FLASH_SMEM>>>();

    // O projection with residual
    mma_gemm_kernel<2><<<dim3(HID / 128, L / 128), 256, GEMM_SMEM>>>(
        pAf, pA8a, pA8b, pWf + OFF_WO, pW8a + OFF_WO, pW8b + OFF_WO,
        out, nullptr, nullptr, HID, x);
}

// round 12
// speedup vs baseline: 1.5304x; 1.5304x over previous
#include <cuda_runtime.h>
#include <cuda_fp16.h>
#include <cstdint>

#define L 2048
#define HID 4096
#define NH 32
#define NKV 8
#define HD 128
#define MAXP 4096

// ---------------------------------------------------------------------------
// PTX helpers (sm_80-class instructions only: valid on baseline sm_103 target)
// ---------------------------------------------------------------------------
__device__ __forceinline__ uint32_t smem_u32(const void* p) {
    uint32_t a;
    asm("{ .reg .u64 t; cvta.to.shared.u64 t, %1; cvt.u32.u64 %0, t; }" : "=r"(a) : "l"(p));
    return a;
}
__device__ __forceinline__ float fast_exp2(float x) {
    float y;
    asm("ex2.approx.f32 %0, %1;" : "=f"(y) : "f"(x));
    return y;
}
#define LDSM_X4(r0, r1, r2, r3, addr)                                              \
    asm volatile("ldmatrix.sync.aligned.m8n8.x4.shared.b16 {%0,%1,%2,%3}, [%4];"   \
                 : "=r"(r0), "=r"(r1), "=r"(r2), "=r"(r3) : "r"(addr))
#define LDSM_X4_T(r0, r1, r2, r3, addr)                                            \
    asm volatile("ldmatrix.sync.aligned.m8n8.x4.trans.shared.b16 {%0,%1,%2,%3}, [%4];" \
                 : "=r"(r0), "=r"(r1), "=r"(r2), "=r"(r3) : "r"(addr))
#define MMA_F16(d, a, b)                                                           \
    asm volatile("mma.sync.aligned.m16n8k16.row.col.f32.f16.f16.f32 "              \
                 "{%0,%1,%2,%3}, {%4,%5,%6,%7}, {%8,%9}, {%0,%1,%2,%3};"           \
                 : "+f"((d)[0]), "+f"((d)[1]), "+f"((d)[2]), "+f"((d)[3])          \
                 : "r"((a)[0]), "r"((a)[1]), "r"((a)[2]), "r"((a)[3]),             \
                   "r"((b)[0]), "r"((b)[1]))
#define CP_ASYNC16(dst, src)                                                       \
    asm volatile("cp.async.cg.shared.global [%0], [%1], 16;" :: "r"(dst), "l"(src))
#define CP_COMMIT() asm volatile("cp.async.commit_group;" ::: "memory")
#define CP_WAIT(n) asm volatile("cp.async.wait_group %0;" :: "n"(n) : "memory")

// ---------------------------------------------------------------------------
// scratch (device globals; no runtime alloc)
// ---------------------------------------------------------------------------
#define NW_TOTAL 41943040
#define OFF_WQ 0
#define OFF_WK 16777216
#define OFF_WV 20971520
#define OFF_WO 25165824

__device__ __half g_ha[(size_t)L * HID];      // rmsnorm out, fp16 hi
__device__ __half g_hl[(size_t)L * HID];      // rmsnorm out, fp16 residual
__device__ __half g_w[(size_t)NW_TOTAL];      // all weights, single fp16
__device__ __half g_aa[(size_t)L * HID];      // attn out, fp16 hi
__device__ __half g_al[(size_t)L * HID];      // attn out, fp16 residual
__device__ __half g_qh[(size_t)L * HID];      // roped+scaled Q hi
__device__ __half g_ql[(size_t)L * HID];      // roped+scaled Q residual
__device__ __half g_kh[(size_t)L * NKV * HD];
__device__ __half g_kl[(size_t)L * NKV * HD];
__device__ __half g_vb[(size_t)L * NKV * HD];
__device__ float g_q[(size_t)L * HID];
__device__ float g_k[(size_t)L * NKV * HD];
__device__ float g_v[(size_t)L * NKV * HD];

__device__ __forceinline__ void split_f16(float x, __half& hi, __half& lo) {
    hi = __float2half_rn(x);
    lo = __float2half_rn(x - __half2float(hi));
}
__device__ __forceinline__ uint32_t pack_f16(float lo, float hi) {
    __half2 t = __floats2half2_rn(lo, hi);  // .x = lo bits [15:0]
    return *(uint32_t*)&t;
}

// ---------------------------------------------------------------------------
// cache copy — rows [L, MAXP) only (rope_kv fully writes rows [0, L))
// ---------------------------------------------------------------------------
__global__ void copy_caches_kernel(const float4* __restrict__ kin,
                                   const float4* __restrict__ vin,
                                   float4* __restrict__ kout,
                                   float4* __restrict__ vout) {
    int idx = blockIdx.x * 256 + threadIdx.x;
    const int n4 = (MAXP - L) * NKV * HD / 4;
    const int off = L * NKV * HD / 4;
    if (idx < n4) kout[off + idx] = kin[off + idx];
    else vout[off + idx - n4] = vin[off + idx - n4];
}

// ---------------------------------------------------------------------------
// fused weight convert: fp32 -> single fp16 (all 4 weights, one launch)
// ---------------------------------------------------------------------------
__global__ void convert_all_kernel(const float4* __restrict__ wq,
                                   const float4* __restrict__ wk,
                                   const float4* __restrict__ wv,
                                   const float4* __restrict__ wo,
                                   __half* __restrict__ w) {
    int i = blockIdx.x * 256 + threadIdx.x;  // [0, NW_TOTAL/4)
    const float4* src;
    int base;
    if (i < OFF_WK / 4) { src = wq; base = 0; }
    else if (i < OFF_WV / 4) { src = wk; base = OFF_WK / 4; }
    else if (i < OFF_WO / 4) { src = wv; base = OFF_WV / 4; }
    else { src = wo; base = OFF_WO / 4; }
    float4 v = src[i - base];
    __half2* hp = (__half2*)(w + (size_t)i * 4);
    hp[0] = __floats2half2_rn(v.x, v.y);
    hp[1] = __floats2half2_rn(v.z, v.w);
}

// ---------------------------------------------------------------------------
// RMSNorm -> exact fp16 pair
// ---------------------------------------------------------------------------
__global__ void __launch_bounds__(256) rmsnorm_kernel(const float* __restrict__ x,
                                                      const float* __restrict__ w) {
    int row = blockIdx.x;
    const float* xr = x + (size_t)row * HID;
    int t = threadIdx.x;
    float vals[16];
    float local = 0.f;
#pragma unroll
    for (int i = 0; i < 16; ++i) {
        float v = xr[t + i * 256];
        vals[i] = v;
        local += v * v;
    }
    __shared__ float red[8];
#pragma unroll
    for (int o = 16; o; o >>= 1) local += __shfl_xor_sync(0xffffffffu, local, o);
    if ((t & 31) == 0) red[t >> 5] = local;
    __syncthreads();
    if (t < 8) {
        float v = red[t];
#pragma unroll
        for (int o = 4; o; o >>= 1) v += __shfl_xor_sync(0xffu, v, o);
        if (t == 0) red[0] = v;
    }
    __syncthreads();
    float rms = rsqrtf(red[0] / (float)HID + 1e-5f);
    size_t base = (size_t)row * HID;
#pragma unroll
    for (int i = 0; i < 16; ++i) {
        float y = vals[i] * rms * w[t + i * 256];
        __half h, l;
        split_f16(y, h, l);
        g_ha[base + t + i * 256] = h;
        g_hl[base + t + i * 256] = l;
    }
}

// ---------------------------------------------------------------------------
// fp16 2-term GEMM: C = (Ah+Al) B^T (+res). A exact fp16 pair, B single fp16.
// CTA 128x256, 512 threads (16 warps 4x4), warp tile 32x64, K-chunk 64,
// 2-stage cp.async. 2 MMA units per logical MAC (was 3) -> 1/3 fewer MACs
// on the MAC-rate-bound mma.sync path.
// MODE 1: fused QKV (N=6144; route q/k/v).  MODE 2: +res.
// ---------------------------------------------------------------------------
#define GSTRIDE 144
#define ATILE 18432            // 128 * 144
#define BOFF  36864            // 2 * ATILE
#define BTILE 36864            // 256 * 144
#define GSTAGE 73728           // 2*ATILE + BTILE
#define GEMM_SMEM (2 * GSTAGE) // 147456
#define GTHREADS 512

template <int MODE>
__global__ void __launch_bounds__(GTHREADS, 1) mma_gemm_kernel(
    const __half* __restrict__ Ah, const __half* __restrict__ Al,
    const __half* __restrict__ B,
    float* __restrict__ C, float* __restrict__ Ck, float* __restrict__ Cvv,
    int N, const float* __restrict__ res) {
    extern __shared__ char sm[];
    const uint32_t sb = smem_u32(sm);
    const int tid = threadIdx.x;
    const int lane = tid & 31, w = tid >> 5;
    const int wm = w >> 2, wn = w & 3;          // 4 x 4 warps, warp tile 32x64
    const int bm = blockIdx.y * 128, bn = blockIdx.x * 256;

    float acc[2][8][4];
#pragma unroll
    for (int a = 0; a < 2; ++a)
#pragma unroll
        for (int b = 0; b < 8; ++b)
#pragma unroll
            for (int c = 0; c < 4; ++c) acc[a][b][c] = 0.f;

    auto issue = [&](int c, int s) {
#pragma unroll
        for (int j = 0; j < 4; ++j) {            // A hi/lo: 2 x 1024 chunks
            const int term = j >> 1;
            const int local = tid + (j & 1) * GTHREADS;  // 0..1023
            const int row = local >> 3;
            const int seg = local & 7;
            const __half* src = term ? Al : Ah;
            const void* g = src + (size_t)(bm + row) * HID + c * 64 + seg * 8;
            uint32_t dst = sb + s * GSTAGE + term * ATILE + row * GSTRIDE + seg * 16;
            CP_ASYNC16(dst, g);
        }
#pragma unroll
        for (int j = 0; j < 4; ++j) {            // B: 2048 chunks
            const int local = tid + j * GTHREADS;        // 0..2047
            const int row = local >> 3;
            const int seg = local & 7;
            const void* g = B + (size_t)(bn + row) * HID + c * 64 + seg * 8;
            uint32_t dst = sb + s * GSTAGE + BOFF + row * GSTRIDE + seg * 16;
            CP_ASYNC16(dst, g);
        }
    };

    auto compute = [&](int s) {
        const uint32_t base = sb + s * GSTAGE;
        const int rsel = lane & 15;
        const int csel = (lane >> 4) << 4;
#pragma unroll
        for (int ks = 0; ks < 4; ++ks) {
            uint32_t ah[2][4], al[2][4];
#pragma unroll
            for (int mt = 0; mt < 2; ++mt) {
                uint32_t ad = base + (wm * 32 + mt * 16 + rsel) * GSTRIDE + ks * 32 + csel;
                LDSM_X4(ah[mt][0], ah[mt][1], ah[mt][2], ah[mt][3], ad);
                LDSM_X4(al[mt][0], al[mt][1], al[mt][2], al[mt][3], ad + ATILE);
            }
#pragma unroll
            for (int half = 0; half < 2; ++half) {
                uint32_t b[4][2];
#pragma unroll
                for (int g = 0; g < 2; ++g) {
                    uint32_t bd = base + BOFF +
                                  (wn * 64 + (half * 2 + g) * 16 + rsel) * GSTRIDE +
                                  ks * 32 + csel;
                    uint32_t t0, t1, t2, t3;
                    LDSM_X4(t0, t1, t2, t3, bd);
                    b[2 * g][0] = t0; b[2 * g][1] = t2;
                    b[2 * g + 1][0] = t1; b[2 * g + 1][1] = t3;
                }
#pragma unroll
                for (int nt = 0; nt < 4; ++nt)
#pragma unroll
                    for (int mt = 0; mt < 2; ++mt)
                        MMA_F16(acc[mt][half * 4 + nt], ah[mt], b[nt]);
#pragma unroll
                for (int nt = 0; nt < 4; ++nt)
#pragma unroll
                    for (int mt = 0; mt < 2; ++mt)
                        MMA_F16(acc[mt][half * 4 + nt], al[mt], b[nt]);
            }
        }
    };

    issue(0, 0); CP_COMMIT();
    issue(1, 1); CP_COMMIT();
#pragma unroll 1
    for (int c = 0; c < 64; ++c) {
        if (c + 1 < 64) { CP_WAIT(1); } else { CP_WAIT(0); }
        __syncthreads();
        compute(c & 1);
        if (c + 2 < 64) {
            __syncthreads();
            issue(c + 2, c & 1);
            CP_COMMIT();
        }
    }

    // epilogue: route output
    float* Cout = C;
    int ncols = N, bnl = bn;
    if (MODE == 1) {
        if (bn < 4096) { Cout = C; ncols = 4096; bnl = bn; }
        else if (bn < 5120) { Cout = Ck; ncols = 1024; bnl = bn - 4096; }
        else { Cout = Cvv; ncols = 1024; bnl = bn - 5120; }
    }
#pragma unroll
    for (int mt = 0; mt < 2; ++mt)
#pragma unroll
        for (int nt = 0; nt < 8; ++nt) {
            int row = bm + wm * 32 + mt * 16 + (lane >> 2);
            int col = bnl + wn * 64 + nt * 8 + ((lane & 3) << 1);
            size_t o0 = (size_t)row * ncols + col;
            size_t o1 = (size_t)(row + 8) * ncols + col;
            float2 v0 = make_float2(acc[mt][nt][0], acc[mt][nt][1]);
            float2 v1 = make_float2(acc[mt][nt][2], acc[mt][nt][3]);
            if (MODE == 2) {
                float2 r0 = *(const float2*)&res[o0];
                float2 r1 = *(const float2*)&res[o1];
                v0.x += r0.x; v0.y += r0.y;
                v1.x += r1.x; v1.y += r1.y;
            }
            *(float2*)&Cout[o0] = v0;
            *(float2*)&Cout[o1] = v1;
        }
}

// ---------------------------------------------------------------------------
// RoPE Q: fp32 -> scaled (1/sqrt(hd) * log2e) exact fp16 pair
// ---------------------------------------------------------------------------
__global__ void rope_q_kernel(const float* __restrict__ cosb, const float* __restrict__ sinb) {
    const float QS = 0.08838834764831845f * 1.4426950408889634f;
    int idx = blockIdx.x * 256 + threadIdx.x;
    int d = idx & 63;
    int h = (idx >> 6) & (NH - 1);
    int i = idx >> 11;
    const float* qp = g_q + (size_t)i * HID + h * HD;
    float c0 = cosb[i * HD + d], s0 = sinb[i * HD + d];
    float c1 = cosb[i * HD + d + 64], s1 = sinb[i * HD + d + 64];
    float q0 = qp[d], q1 = qp[d + 64];
    float r0 = (q0 * c0 - q1 * s0) * QS;
    float r1 = (q1 * c1 + q0 * s1) * QS;
    size_t base = (size_t)i * HID + h * HD;
    __half hh, ll;
    split_f16(r0, hh, ll);
    g_qh[base + d] = hh; g_ql[base + d] = ll;
    split_f16(r1, hh, ll);
    g_qh[base + d + 64] = hh; g_ql[base + d + 64] = ll;
}

// RoPE K + scatter fp32 caches + exact fp16 K pair, fp16 V
__global__ void rope_kv_kernel(const float* __restrict__ cosb, const float* __restrict__ sinb,
                               float* __restrict__ kc_out, float* __restrict__ vc_out) {
    int idx = blockIdx.x * 256 + threadIdx.x;
    int d = idx & 63;
    int h = (idx >> 6) & (NKV - 1);
    int i = idx >> 9;
    size_t base = (size_t)i * (NKV * HD) + h * HD;
    float c0 = cosb[i * HD + d], s0 = sinb[i * HD + d];
    float c1 = cosb[i * HD + d + 64], s1 = sinb[i * HD + d + 64];
    float k0 = g_k[base + d], k1 = g_k[base + d + 64];
    float k0n = k0 * c0 - k1 * s0;
    float k1n = k1 * c1 + k0 * s1;
    kc_out[base + d] = k0n;
    kc_out[base + d + 64] = k1n;
    __half hh, ll;
    split_f16(k0n, hh, ll);
    g_kh[base + d] = hh; g_kl[base + d] = ll;
    split_f16(k1n, hh, ll);
    g_kh[base + d + 64] = hh; g_kl[base + d + 64] = ll;
    float v0 = g_v[base + d], v1 = g_v[base + d + 64];
    vc_out[base + d] = v0;
    vc_out[base + d + 64] = v1;
    g_vb[base + d] = __float2half_rn(v0);
    g_vb[base + d + 64] = __float2half_rn(v1);
}

// ---------------------------------------------------------------------------
// Flash attention via fp16 mma: BM=128 (8 warps x m16), BN=64, HD=128.
// QK^T: exact fp16 pairs, 3 mma terms (qh kh + qh kl + ql kh; error ~2^-22).
// softmax fp32 exp2 (scale folded into Q); P fp16; PV fp16 via ldmatrix.trans.
// Split cp.async waits: V load overlaps the whole S-phase.
// ---------------------------------------------------------------------------
#define FSTRIDE 272
#define FQH 0
#define FQL 34816
#define FKH 69632
#define FKL 87040
#define FV 104448
#define FLASH_SMEM 121856

__global__ void __launch_bounds__(256, 1) flash_kernel() {
    extern __shared__ char sm[];
    const uint32_t sb = smem_u32(sm);
    const int tid = threadIdx.x;
    const int lane = tid & 31, w = tid >> 5;
    const int qt = gridDim.x - 1 - blockIdx.x;  // heavy tiles first
    const int head = blockIdx.y;
    const int kvh = head >> 2;
    const int rsel = lane & 15;
    const int csel = (lane >> 4) << 4;

#pragma unroll
    for (int j = 0; j < 16; ++j) {
        const int term = j >> 3;
        const int local = tid + (j & 7) * 256;
        const int row = local >> 4;
        const int seg = local & 15;
        const __half* src = (term ? g_ql : g_qh);
        const void* g = src + (size_t)(qt * 128 + row) * HID + head * HD + seg * 8;
        uint32_t dst = sb + (term ? FQL : FQH) + row * FSTRIDE + seg * 16;
        CP_ASYNC16(dst, g);
    }
    CP_COMMIT();

    float o_[16][4];
#pragma unroll
    for (int n = 0; n < 16; ++n)
#pragma unroll
        for (int c = 0; c < 4; ++c) o_[n][c] = 0.f;
    float m_[2] = {-1e30f, -1e30f};
    float l_[2] = {0.f, 0.f};

    const int kt_end = 2 * qt + 2;
#pragma unroll 1
    for (int kt = 0; kt < kt_end; ++kt) {
        __syncthreads();
#pragma unroll
        for (int j = 0; j < 8; ++j) {
            const int t = j >> 2;
            const int local = tid + (j & 3) * 256;
            const int row = local >> 4;
            const int seg = local & 15;
            const __half* src = (t == 0) ? g_kh : g_kl;
            const void* g = src + (size_t)(kt * 64 + row) * (NKV * HD) + kvh * HD + seg * 8;
            uint32_t dst = sb + ((t == 0) ? FKH : FKL) + row * FSTRIDE + seg * 16;
            CP_ASYNC16(dst, g);
        }
        CP_COMMIT();
#pragma unroll
        for (int j = 0; j < 4; ++j) {
            const int local = tid + j * 256;
            const int row = local >> 4;
            const int seg = local & 15;
            const void* g = g_vb + (size_t)(kt * 64 + row) * (NKV * HD) + kvh * HD + seg * 8;
            uint32_t dst = sb + FV + row * FSTRIDE + seg * 16;
            CP_ASYNC16(dst, g);
        }
        CP_COMMIT();

        CP_WAIT(1);
        __syncthreads();

        float s[8][4];
#pragma unroll
        for (int n = 0; n < 8; ++n)
#pragma unroll
            for (int c = 0; c < 4; ++c) s[n][c] = 0.f;
#pragma unroll
        for (int ks = 0; ks < 8; ++ks) {
            uint32_t ah[4], al[4];
            uint32_t aaddr = sb + FQH + (w * 16 + rsel) * FSTRIDE + ks * 32 + csel;
            LDSM_X4(ah[0], ah[1], ah[2], ah[3], aaddr);
            LDSM_X4(al[0], al[1], al[2], al[3], aaddr + (FQL - FQH));
#pragma unroll
            for (int half = 0; half < 2; ++half) {
                uint32_t bh[4][2], bl[4][2];
#pragma unroll
                for (int g = 0; g < 2; ++g) {
                    uint32_t bd = sb + FKH +
                                  ((half * 2 + g) * 16 + rsel) * FSTRIDE + ks * 32 + csel;
                    uint32_t t0, t1, t2, t3;
                    LDSM_X4(t0, t1, t2, t3, bd);
                    bh[2 * g][0] = t0; bh[2 * g][1] = t2;
                    bh[2 * g + 1][0] = t1; bh[2 * g + 1][1] = t3;
                    LDSM_X4(t0, t1, t2, t3, bd + (FKL - FKH));
                    bl[2 * g][0] = t0; bl[2 * g][1] = t2;
                    bl[2 * g + 1][0] = t1; bl[2 * g + 1][1] = t3;
                }
#pragma unroll
                for (int n = 0; n < 4; ++n) MMA_F16(s[half * 4 + n], ah, bh[n]);
#pragma unroll
                for (int n = 0; n < 4; ++n) MMA_F16(s[half * 4 + n], ah, bl[n]);
#pragma unroll
                for (int n = 0; n < 4; ++n) MMA_F16(s[half * 4 + n], al, bh[n]);
            }
        }

        if (kt >= 2 * qt) {
            const int r0g = qt * 128 + w * 16 + (lane >> 2);
#pragma unroll
            for (int j = 0; j < 8; ++j) {
                int cb = kt * 64 + j * 8 + ((lane & 3) << 1);
                if (cb > r0g) s[j][0] = -1e30f;
                if (cb + 1 > r0g) s[j][1] = -1e30f;
                if (cb > r0g + 8) s[j][2] = -1e30f;
                if (cb + 1 > r0g + 8) s[j][3] = -1e30f;
            }
        }

#pragma unroll
        for (int i = 0; i < 2; ++i) {
            float mt_ = -1e30f;
#pragma unroll
            for (int j = 0; j < 8; ++j)
                mt_ = fmaxf(mt_, fmaxf(s[j][2 * i], s[j][2 * i + 1]));
            mt_ = fmaxf(mt_, __shfl_xor_sync(0xffffffffu, mt_, 1));
            mt_ = fmaxf(mt_, __shfl_xor_sync(0xffffffffu, mt_, 2));
            float mn = fmaxf(m_[i], mt_);
            float corr = fast_exp2(m_[i] - mn);
            m_[i] = mn;
            float rs = 0.f;
#pragma unroll
            for (int j = 0; j < 8; ++j) {
                float p0 = fast_exp2(s[j][2 * i] - mn);
                float p1 = fast_exp2(s[j][2 * i + 1] - mn);
                s[j][2 * i] = p0;
                s[j][2 * i + 1] = p1;
                rs += p0 + p1;
            }
            rs += __shfl_xor_sync(0xffffffffu, rs, 1);
            rs += __shfl_xor_sync(0xffffffffu, rs, 2);
            l_[i] = l_[i] * corr + rs;
#pragma unroll
            for (int n = 0; n < 16; ++n) {
                o_[n][2 * i] *= corr;
                o_[n][2 * i + 1] *= corr;
            }
        }

        uint32_t pa[4][4];
#pragma unroll
        for (int t = 0; t < 4; ++t) {
            pa[t][0] = pack_f16(s[2 * t][0], s[2 * t][1]);
            pa[t][1] = pack_f16(s[2 * t][2], s[2 * t][3]);
            pa[t][2] = pack_f16(s[2 * t + 1][0], s[2 * t + 1][1]);
            pa[t][3] = pack_f16(s[2 * t + 1][2], s[2 * t + 1][3]);
        }

        CP_WAIT(0);
        __syncthreads();

#pragma unroll
        for (int t = 0; t < 4; ++t) {
#pragma unroll
            for (int g = 0; g < 8; ++g) {
                uint32_t vaddr = sb + FV + (t * 16 + rsel) * FSTRIDE +
                                 (g * 16 + ((lane >> 4) << 3)) * 2;
                uint32_t t0, t1, t2, t3;
                LDSM_X4_T(t0, t1, t2, t3, vaddr);
                uint32_t b0[2] = {t0, t1}, b1[2] = {t2, t3};
                MMA_F16(o_[2 * g], pa[t], b0);
                MMA_F16(o_[2 * g + 1], pa[t], b1);
            }
        }
    }

    // epilogue: normalize and emit exact fp16 pair for the O projection
    const float inv0 = 1.f / l_[0];
    const float inv1 = 1.f / l_[1];
    const int r0g = qt * 128 + w * 16 + (lane >> 2);
#pragma unroll
    for (int nt = 0; nt < 16; ++nt) {
        int col = head * HD + nt * 8 + ((lane & 3) << 1);
        size_t o0 = (size_t)r0g * HID + col;
        size_t o1 = o0 + (size_t)8 * HID;
        __half h0, l0, h1, l1;
        split_f16(o_[nt][0] * inv0, h0, l0);
        split_f16(o_[nt][1] * inv0, h1, l1);
        *(__half2*)(g_aa + o0) = __halves2half2(h0, h1);
        *(__half2*)(g_al + o0) = __halves2half2(l0, l1);
        split_f16(o_[nt][2] * inv1, h0, l0);
        split_f16(o_[nt][3] * inv1, h1, l1);
        *(__half2*)(g_aa + o1) = __halves2half2(h0, h1);
        *(__half2*)(g_al + o1) = __halves2half2(l0, l1);
    }
}

// ---------------------------------------------------------------------------
// launch
// ---------------------------------------------------------------------------
extern "C" void kernel_launch(void* const* d_in, const int* in_sizes, int n_in,
                              void* d_out, int out_size) {
    const float* x = (const float*)d_in[0];
    const float* cosb = (const float*)d_in[1];
    const float* sinb = (const float*)d_in[2];
    // d_in[3] position_ids (arange; not dereferenced), d_in[4] seq_len
    const float* kc_in = (const float*)d_in[5];
    const float* vc_in = (const float*)d_in[6];
    const float* lnw = (const float*)d_in[7];
    const float* Wq = (const float*)d_in[8];
    const float* Wk = (const float*)d_in[9];
    const float* Wv = (const float*)d_in[10];
    const float* Wo = (const float*)d_in[11];

    float* out = (float*)d_out;
    float* kc_out = out + (size_t)L * HID;
    float* vc_out = kc_out + (size_t)MAXP * NKV * HD;

    __half *pHa, *pHl, *pW, *pAa, *pAl;
    float *pQ, *pK, *pV;
    cudaGetSymbolAddress((void**)&pHa, g_ha);
    cudaGetSymbolAddress((void**)&pHl, g_hl);
    cudaGetSymbolAddress((void**)&pW, g_w);
    cudaGetSymbolAddress((void**)&pAa, g_aa);
    cudaGetSymbolAddress((void**)&pAl, g_al);
    cudaGetSymbolAddress((void**)&pQ, g_q);
    cudaGetSymbolAddress((void**)&pK, g_k);
    cudaGetSymbolAddress((void**)&pV, g_v);

    copy_caches_kernel<<<(2 * (MAXP - L) * NKV * HD / 4) / 256, 256>>>(
        (const float4*)kc_in, (const float4*)vc_in, (float4*)kc_out, (float4*)vc_out);

    convert_all_kernel<<<(NW_TOTAL / 4) / 256, 256>>>(
        (const float4*)Wq, (const float4*)Wk, (const float4*)Wv, (const float4*)Wo, pW);

    rmsnorm_kernel<<<L, 256>>>(x, lnw);

    cudaFuncSetAttribute((const void*)mma_gemm_kernel<1>,
                         cudaFuncAttributeMaxDynamicSharedMemorySize, GEMM_SMEM);
    cudaFuncSetAttribute((const void*)mma_gemm_kernel<2>,
                         cudaFuncAttributeMaxDynamicSharedMemorySize, GEMM_SMEM);

    // fused Q+K+V projection: N = 6144, grid (24, 16)
    mma_gemm_kernel<1><<<dim3(6144 / 256, L / 128), GTHREADS, GEMM_SMEM>>>(
        pHa, pHl, pW, pQ, pK, pV, 6144, nullptr);

    rope_q_kernel<<<(L * NH * 64) / 256, 256>>>(cosb, sinb);
    rope_kv_kernel<<<(L * NKV * 64) / 256, 256>>>(cosb, sinb, kc_out, vc_out);

    cudaFuncSetAttribute(flash_kernel, cudaFuncAttributeMaxDynamicSharedMemorySize, FLASH_SMEM);
    flash_kernel<<<dim3(L / 128, NH), 256, FLASH_SMEM>>>();

    // O projection with residual
    mma_gemm_kernel<2><<<dim3(HID / 256, L / 128), GTHREADS, GEMM_SMEM>>>(
        pAa, pAl, pW + OFF_WO, out, nullptr, nullptr, HID, x);
}

// round 13
// speedup vs baseline: 1.8656x; 1.2190x over previous
#include <cuda_runtime.h>
#include <cuda_fp16.h>
#include <cstdint>

#define L 2048
#define HID 4096
#define NH 32
#define NKV 8
#define HD 128
#define MAXP 4096

// ---------------------------------------------------------------------------
// PTX helpers (sm_80-class instructions only: valid on baseline sm_103 target)
// ---------------------------------------------------------------------------
__device__ __forceinline__ uint32_t smem_u32(const void* p) {
    uint32_t a;
    asm("{ .reg .u64 t; cvta.to.shared.u64 t, %1; cvt.u32.u64 %0, t; }" : "=r"(a) : "l"(p));
    return a;
}
__device__ __forceinline__ float fast_exp2(float x) {
    float y;
    asm("ex2.approx.f32 %0, %1;" : "=f"(y) : "f"(x));
    return y;
}
#define LDSM_X4(r0, r1, r2, r3, addr)                                              \
    asm volatile("ldmatrix.sync.aligned.m8n8.x4.shared.b16 {%0,%1,%2,%3}, [%4];"   \
                 : "=r"(r0), "=r"(r1), "=r"(r2), "=r"(r3) : "r"(addr))
#define LDSM_X4_T(r0, r1, r2, r3, addr)                                            \
    asm volatile("ldmatrix.sync.aligned.m8n8.x4.trans.shared.b16 {%0,%1,%2,%3}, [%4];" \
                 : "=r"(r0), "=r"(r1), "=r"(r2), "=r"(r3) : "r"(addr))
#define MMA_F16(d, a, b)                                                           \
    asm volatile("mma.sync.aligned.m16n8k16.row.col.f32.f16.f16.f32 "              \
                 "{%0,%1,%2,%3}, {%4,%5,%6,%7}, {%8,%9}, {%0,%1,%2,%3};"           \
                 : "+f"((d)[0]), "+f"((d)[1]), "+f"((d)[2]), "+f"((d)[3])          \
                 : "r"((a)[0]), "r"((a)[1]), "r"((a)[2]), "r"((a)[3]),             \
                   "r"((b)[0]), "r"((b)[1]))
#define CP_ASYNC16(dst, src)                                                       \
    asm volatile("cp.async.cg.shared.global [%0], [%1], 16;" :: "r"(dst), "l"(src))
#define CP_COMMIT() asm volatile("cp.async.commit_group;" ::: "memory")
#define CP_WAIT(n) asm volatile("cp.async.wait_group %0;" :: "n"(n) : "memory")

// ---------------------------------------------------------------------------
// scratch (device globals; no runtime alloc)
// ---------------------------------------------------------------------------
#define NW_TOTAL 41943040
#define OFF_WQ 0
#define OFF_WK 16777216
#define OFF_WV 20971520
#define OFF_WO 25165824

__device__ __half g_ha[(size_t)L * HID];      // rmsnorm out, fp16 hi
__device__ __half g_hl[(size_t)L * HID];      // rmsnorm out, fp16 residual
__device__ __half g_w[(size_t)NW_TOTAL];      // all weights, single fp16
__device__ __half g_aa[(size_t)L * HID];      // attn out, single fp16
__device__ __half g_qh[(size_t)L * HID];      // roped+scaled Q hi
__device__ __half g_ql[(size_t)L * HID];      // roped+scaled Q residual
__device__ __half g_kh[(size_t)L * NKV * HD]; // roped K, single fp16
__device__ __half g_vb[(size_t)L * NKV * HD]; // V, single fp16
__device__ float g_q[(size_t)L * HID];
__device__ float g_k[(size_t)L * NKV * HD];
__device__ float g_v[(size_t)L * NKV * HD];

__device__ __forceinline__ void split_f16(float x, __half& hi, __half& lo) {
    hi = __float2half_rn(x);
    lo = __float2half_rn(x - __half2float(hi));
}
__device__ __forceinline__ uint32_t pack_f16(float lo, float hi) {
    __half2 t = __floats2half2_rn(lo, hi);  // .x = lo bits [15:0]
    return *(uint32_t*)&t;
}

// ---------------------------------------------------------------------------
// cache copy — rows [L, MAXP) only (rope_kv fully writes rows [0, L))
// ---------------------------------------------------------------------------
__global__ void copy_caches_kernel(const float4* __restrict__ kin,
                                   const float4* __restrict__ vin,
                                   float4* __restrict__ kout,
                                   float4* __restrict__ vout) {
    int idx = blockIdx.x * 256 + threadIdx.x;
    const int n4 = (MAXP - L) * NKV * HD / 4;
    const int off = L * NKV * HD / 4;
    if (idx < n4) kout[off + idx] = kin[off + idx];
    else vout[off + idx - n4] = vin[off + idx - n4];
}

// ---------------------------------------------------------------------------
// fused weight convert: fp32 -> single fp16 (all 4 weights, one launch)
// ---------------------------------------------------------------------------
__global__ void convert_all_kernel(const float4* __restrict__ wq,
                                   const float4* __restrict__ wk,
                                   const float4* __restrict__ wv,
                                   const float4* __restrict__ wo,
                                   __half* __restrict__ w) {
    int i = blockIdx.x * 256 + threadIdx.x;  // [0, NW_TOTAL/4)
    const float4* src;
    int base;
    if (i < OFF_WK / 4) { src = wq; base = 0; }
    else if (i < OFF_WV / 4) { src = wk; base = OFF_WK / 4; }
    else if (i < OFF_WO / 4) { src = wv; base = OFF_WV / 4; }
    else { src = wo; base = OFF_WO / 4; }
    float4 v = src[i - base];
    __half2* hp = (__half2*)(w + (size_t)i * 4);
    hp[0] = __floats2half2_rn(v.x, v.y);
    hp[1] = __floats2half2_rn(v.z, v.w);
}

// ---------------------------------------------------------------------------
// RMSNorm -> exact fp16 pair
// ---------------------------------------------------------------------------
__global__ void __launch_bounds__(256) rmsnorm_kernel(const float* __restrict__ x,
                                                      const float* __restrict__ w) {
    int row = blockIdx.x;
    const float* xr = x + (size_t)row * HID;
    int t = threadIdx.x;
    float vals[16];
    float local = 0.f;
#pragma unroll
    for (int i = 0; i < 16; ++i) {
        float v = xr[t + i * 256];
        vals[i] = v;
        local += v * v;
    }
    __shared__ float red[8];
#pragma unroll
    for (int o = 16; o; o >>= 1) local += __shfl_xor_sync(0xffffffffu, local, o);
    if ((t & 31) == 0) red[t >> 5] = local;
    __syncthreads();
    if (t < 8) {
        float v = red[t];
#pragma unroll
        for (int o = 4; o; o >>= 1) v += __shfl_xor_sync(0xffu, v, o);
        if (t == 0) red[0] = v;
    }
    __syncthreads();
    float rms = rsqrtf(red[0] / (float)HID + 1e-5f);
    size_t base = (size_t)row * HID;
#pragma unroll
    for (int i = 0; i < 16; ++i) {
        float y = vals[i] * rms * w[t + i * 256];
        __half h, l;
        split_f16(y, h, l);
        g_ha[base + t + i * 256] = h;
        g_hl[base + t + i * 256] = l;
    }
}

// ---------------------------------------------------------------------------
// fp16 GEMM: C = A B^T (+res). TERMS=2: A exact fp16 pair. TERMS=1: single.
// B single fp16. CTA 128x256, 512 threads (16 warps 4x4), warp tile 32x64,
// K-chunk 64, 2-stage cp.async. MAC-rate-bound: time ~ TERMS.
// MODE 1: fused QKV (N=6144; route q/k/v).  MODE 2: +res.
// ---------------------------------------------------------------------------
#define GSTRIDE 144
#define ATILE 18432            // 128 * 144
#define BOFF  36864            // 2 * ATILE
#define BTILE 36864            // 256 * 144
#define GSTAGE 73728           // 2*ATILE + BTILE
#define GEMM_SMEM (2 * GSTAGE) // 147456
#define GTHREADS 512

template <int MODE, int TERMS>
__global__ void __launch_bounds__(GTHREADS, 1) mma_gemm_kernel(
    const __half* __restrict__ Ah, const __half* __restrict__ Al,
    const __half* __restrict__ B,
    float* __restrict__ C, float* __restrict__ Ck, float* __restrict__ Cvv,
    int N, const float* __restrict__ res) {
    extern __shared__ char sm[];
    const uint32_t sb = smem_u32(sm);
    const int tid = threadIdx.x;
    const int lane = tid & 31, w = tid >> 5;
    const int wm = w >> 2, wn = w & 3;          // 4 x 4 warps, warp tile 32x64
    const int bm = blockIdx.y * 128, bn = blockIdx.x * 256;

    float acc[2][8][4];
#pragma unroll
    for (int a = 0; a < 2; ++a)
#pragma unroll
        for (int b = 0; b < 8; ++b)
#pragma unroll
            for (int c = 0; c < 4; ++c) acc[a][b][c] = 0.f;

    auto issue = [&](int c, int s) {
#pragma unroll
        for (int j = 0; j < 2 * TERMS; ++j) {    // A: TERMS x 1024 chunks
            const int term = j >> 1;
            const int local = tid + (j & 1) * GTHREADS;  // 0..1023
            const int row = local >> 3;
            const int seg = local & 7;
            const __half* src = term ? Al : Ah;
            const void* g = src + (size_t)(bm + row) * HID + c * 64 + seg * 8;
            uint32_t dst = sb + s * GSTAGE + term * ATILE + row * GSTRIDE + seg * 16;
            CP_ASYNC16(dst, g);
        }
#pragma unroll
        for (int j = 0; j < 4; ++j) {            // B: 2048 chunks
            const int local = tid + j * GTHREADS;        // 0..2047
            const int row = local >> 3;
            const int seg = local & 7;
            const void* g = B + (size_t)(bn + row) * HID + c * 64 + seg * 8;
            uint32_t dst = sb + s * GSTAGE + BOFF + row * GSTRIDE + seg * 16;
            CP_ASYNC16(dst, g);
        }
    };

    auto compute = [&](int s) {
        const uint32_t base = sb + s * GSTAGE;
        const int rsel = lane & 15;
        const int csel = (lane >> 4) << 4;
#pragma unroll
        for (int ks = 0; ks < 4; ++ks) {
            uint32_t ah[2][4], al[2][4];
#pragma unroll
            for (int mt = 0; mt < 2; ++mt) {
                uint32_t ad = base + (wm * 32 + mt * 16 + rsel) * GSTRIDE + ks * 32 + csel;
                LDSM_X4(ah[mt][0], ah[mt][1], ah[mt][2], ah[mt][3], ad);
                if (TERMS == 2) {
                    LDSM_X4(al[mt][0], al[mt][1], al[mt][2], al[mt][3], ad + ATILE);
                }
            }
#pragma unroll
            for (int half = 0; half < 2; ++half) {
                uint32_t b[4][2];
#pragma unroll
                for (int g = 0; g < 2; ++g) {
                    uint32_t bd = base + BOFF +
                                  (wn * 64 + (half * 2 + g) * 16 + rsel) * GSTRIDE +
                                  ks * 32 + csel;
                    uint32_t t0, t1, t2, t3;
                    LDSM_X4(t0, t1, t2, t3, bd);
                    b[2 * g][0] = t0; b[2 * g][1] = t2;
                    b[2 * g + 1][0] = t1; b[2 * g + 1][1] = t3;
                }
#pragma unroll
                for (int nt = 0; nt < 4; ++nt)
#pragma unroll
                    for (int mt = 0; mt < 2; ++mt)
                        MMA_F16(acc[mt][half * 4 + nt], ah[mt], b[nt]);
                if (TERMS == 2) {
#pragma unroll
                    for (int nt = 0; nt < 4; ++nt)
#pragma unroll
                        for (int mt = 0; mt < 2; ++mt)
                            MMA_F16(acc[mt][half * 4 + nt], al[mt], b[nt]);
                }
            }
        }
    };

    issue(0, 0); CP_COMMIT();
    issue(1, 1); CP_COMMIT();
#pragma unroll 1
    for (int c = 0; c < 64; ++c) {
        if (c + 1 < 64) { CP_WAIT(1); } else { CP_WAIT(0); }
        __syncthreads();
        compute(c & 1);
        if (c + 2 < 64) {
            __syncthreads();
            issue(c + 2, c & 1);
            CP_COMMIT();
        }
    }

    // epilogue: route output
    float* Cout = C;
    int ncols = N, bnl = bn;
    if (MODE == 1) {
        if (bn < 4096) { Cout = C; ncols = 4096; bnl = bn; }
        else if (bn < 5120) { Cout = Ck; ncols = 1024; bnl = bn - 4096; }
        else { Cout = Cvv; ncols = 1024; bnl = bn - 5120; }
    }
#pragma unroll
    for (int mt = 0; mt < 2; ++mt)
#pragma unroll
        for (int nt = 0; nt < 8; ++nt) {
            int row = bm + wm * 32 + mt * 16 + (lane >> 2);
            int col = bnl + wn * 64 + nt * 8 + ((lane & 3) << 1);
            size_t o0 = (size_t)row * ncols + col;
            size_t o1 = (size_t)(row + 8) * ncols + col;
            float2 v0 = make_float2(acc[mt][nt][0], acc[mt][nt][1]);
            float2 v1 = make_float2(acc[mt][nt][2], acc[mt][nt][3]);
            if (MODE == 2) {
                float2 r0 = *(const float2*)&res[o0];
                float2 r1 = *(const float2*)&res[o1];
                v0.x += r0.x; v0.y += r0.y;
                v1.x += r1.x; v1.y += r1.y;
            }
            *(float2*)&Cout[o0] = v0;
            *(float2*)&Cout[o1] = v1;
        }
}

// ---------------------------------------------------------------------------
// RoPE Q: fp32 -> scaled (1/sqrt(hd) * log2e) exact fp16 pair
// ---------------------------------------------------------------------------
__global__ void rope_q_kernel(const float* __restrict__ cosb, const float* __restrict__ sinb) {
    const float QS = 0.08838834764831845f * 1.4426950408889634f;
    int idx = blockIdx.x * 256 + threadIdx.x;
    int d = idx & 63;
    int h = (idx >> 6) & (NH - 1);
    int i = idx >> 11;
    const float* qp = g_q + (size_t)i * HID + h * HD;
    float c0 = cosb[i * HD + d], s0 = sinb[i * HD + d];
    float c1 = cosb[i * HD + d + 64], s1 = sinb[i * HD + d + 64];
    float q0 = qp[d], q1 = qp[d + 64];
    float r0 = (q0 * c0 - q1 * s0) * QS;
    float r1 = (q1 * c1 + q0 * s1) * QS;
    size_t base = (size_t)i * HID + h * HD;
    __half hh, ll;
    split_f16(r0, hh, ll);
    g_qh[base + d] = hh; g_ql[base + d] = ll;
    split_f16(r1, hh, ll);
    g_qh[base + d + 64] = hh; g_ql[base + d + 64] = ll;
}

// RoPE K + scatter fp32 caches + single fp16 K, fp16 V
__global__ void rope_kv_kernel(const float* __restrict__ cosb, const float* __restrict__ sinb,
                               float* __restrict__ kc_out, float* __restrict__ vc_out) {
    int idx = blockIdx.x * 256 + threadIdx.x;
    int d = idx & 63;
    int h = (idx >> 6) & (NKV - 1);
    int i = idx >> 9;
    size_t base = (size_t)i * (NKV * HD) + h * HD;
    float c0 = cosb[i * HD + d], s0 = sinb[i * HD + d];
    float c1 = cosb[i * HD + d + 64], s1 = sinb[i * HD + d + 64];
    float k0 = g_k[base + d], k1 = g_k[base + d + 64];
    float k0n = k0 * c0 - k1 * s0;
    float k1n = k1 * c1 + k0 * s1;
    kc_out[base + d] = k0n;
    kc_out[base + d + 64] = k1n;
    g_kh[base + d] = __float2half_rn(k0n);
    g_kh[base + d + 64] = __float2half_rn(k1n);
    float v0 = g_v[base + d], v1 = g_v[base + d + 64];
    vc_out[base + d] = v0;
    vc_out[base + d + 64] = v1;
    g_vb[base + d] = __float2half_rn(v0);
    g_vb[base + d + 64] = __float2half_rn(v1);
}

// ---------------------------------------------------------------------------
// Flash attention via fp16 mma: BM=128 (8 warps x m16), BN=64, HD=128.
// QK^T: Q exact fp16 pair x K single fp16 = 2 mma terms (error ~ q*2^-11 k).
// softmax fp32 exp2 (scale folded into Q); P fp16; PV fp16 via ldmatrix.trans.
// Split cp.async waits: V load overlaps the whole S-phase.
// ---------------------------------------------------------------------------
#define FSTRIDE 272
#define FQH 0
#define FQL 34816
#define FKH 69632
#define FV 87040
#define FLASH_SMEM 104448

__global__ void __launch_bounds__(256, 1) flash_kernel() {
    extern __shared__ char sm[];
    const uint32_t sb = smem_u32(sm);
    const int tid = threadIdx.x;
    const int lane = tid & 31, w = tid >> 5;
    const int qt = gridDim.x - 1 - blockIdx.x;  // heavy tiles first
    const int head = blockIdx.y;
    const int kvh = head >> 2;
    const int rsel = lane & 15;
    const int csel = (lane >> 4) << 4;

#pragma unroll
    for (int j = 0; j < 16; ++j) {
        const int term = j >> 3;
        const int local = tid + (j & 7) * 256;
        const int row = local >> 4;
        const int seg = local & 15;
        const __half* src = (term ? g_ql : g_qh);
        const void* g = src + (size_t)(qt * 128 + row) * HID + head * HD + seg * 8;
        uint32_t dst = sb + (term ? FQL : FQH) + row * FSTRIDE + seg * 16;
        CP_ASYNC16(dst, g);
    }
    CP_COMMIT();

    float o_[16][4];
#pragma unroll
    for (int n = 0; n < 16; ++n)
#pragma unroll
        for (int c = 0; c < 4; ++c) o_[n][c] = 0.f;
    float m_[2] = {-1e30f, -1e30f};
    float l_[2] = {0.f, 0.f};

    const int kt_end = 2 * qt + 2;
#pragma unroll 1
    for (int kt = 0; kt < kt_end; ++kt) {
        __syncthreads();
        // K single fp16 (group: K)
#pragma unroll
        for (int j = 0; j < 4; ++j) {
            const int local = tid + j * 256;
            const int row = local >> 4;
            const int seg = local & 15;
            const void* g = g_kh + (size_t)(kt * 64 + row) * (NKV * HD) + kvh * HD + seg * 8;
            uint32_t dst = sb + FKH + row * FSTRIDE + seg * 16;
            CP_ASYNC16(dst, g);
        }
        CP_COMMIT();
        // V (group: V) — overlaps the S phase below
#pragma unroll
        for (int j = 0; j < 4; ++j) {
            const int local = tid + j * 256;
            const int row = local >> 4;
            const int seg = local & 15;
            const void* g = g_vb + (size_t)(kt * 64 + row) * (NKV * HD) + kvh * HD + seg * 8;
            uint32_t dst = sb + FV + row * FSTRIDE + seg * 16;
            CP_ASYNC16(dst, g);
        }
        CP_COMMIT();

        CP_WAIT(1);
        __syncthreads();

        float s[8][4];
#pragma unroll
        for (int n = 0; n < 8; ++n)
#pragma unroll
            for (int c = 0; c < 4; ++c) s[n][c] = 0.f;
#pragma unroll
        for (int ks = 0; ks < 8; ++ks) {
            uint32_t ah[4], al[4];
            uint32_t aaddr = sb + FQH + (w * 16 + rsel) * FSTRIDE + ks * 32 + csel;
            LDSM_X4(ah[0], ah[1], ah[2], ah[3], aaddr);
            LDSM_X4(al[0], al[1], al[2], al[3], aaddr + (FQL - FQH));
#pragma unroll
            for (int half = 0; half < 2; ++half) {
                uint32_t b[4][2];
#pragma unroll
                for (int g = 0; g < 2; ++g) {
                    uint32_t bd = sb + FKH +
                                  ((half * 2 + g) * 16 + rsel) * FSTRIDE + ks * 32 + csel;
                    uint32_t t0, t1, t2, t3;
                    LDSM_X4(t0, t1, t2, t3, bd);
                    b[2 * g][0] = t0; b[2 * g][1] = t2;
                    b[2 * g + 1][0] = t1; b[2 * g + 1][1] = t3;
                }
#pragma unroll
                for (int n = 0; n < 4; ++n) MMA_F16(s[half * 4 + n], ah, b[n]);
#pragma unroll
                for (int n = 0; n < 4; ++n) MMA_F16(s[half * 4 + n], al, b[n]);
            }
        }

        if (kt >= 2 * qt) {
            const int r0g = qt * 128 + w * 16 + (lane >> 2);
#pragma unroll
            for (int j = 0; j < 8; ++j) {
                int cb = kt * 64 + j * 8 + ((lane & 3) << 1);
                if (cb > r0g) s[j][0] = -1e30f;
                if (cb + 1 > r0g) s[j][1] = -1e30f;
                if (cb > r0g + 8) s[j][2] = -1e30f;
                if (cb + 1 > r0g + 8) s[j][3] = -1e30f;
            }
        }

#pragma unroll
        for (int i = 0; i < 2; ++i) {
            float mt_ = -1e30f;
#pragma unroll
            for (int j = 0; j < 8; ++j)
                mt_ = fmaxf(mt_, fmaxf(s[j][2 * i], s[j][2 * i + 1]));
            mt_ = fmaxf(mt_, __shfl_xor_sync(0xffffffffu, mt_, 1));
            mt_ = fmaxf(mt_, __shfl_xor_sync(0xffffffffu, mt_, 2));
            float mn = fmaxf(m_[i], mt_);
            float corr = fast_exp2(m_[i] - mn);
            m_[i] = mn;
            float rs = 0.f;
#pragma unroll
            for (int j = 0; j < 8; ++j) {
                float p0 = fast_exp2(s[j][2 * i] - mn);
                float p1 = fast_exp2(s[j][2 * i + 1] - mn);
                s[j][2 * i] = p0;
                s[j][2 * i + 1] = p1;
                rs += p0 + p1;
            }
            rs += __shfl_xor_sync(0xffffffffu, rs, 1);
            rs += __shfl_xor_sync(0xffffffffu, rs, 2);
            l_[i] = l_[i] * corr + rs;
#pragma unroll
            for (int n = 0; n < 16; ++n) {
                o_[n][2 * i] *= corr;
                o_[n][2 * i + 1] *= corr;
            }
        }

        uint32_t pa[4][4];
#pragma unroll
        for (int t = 0; t < 4; ++t) {
            pa[t][0] = pack_f16(s[2 * t][0], s[2 * t][1]);
            pa[t][1] = pack_f16(s[2 * t][2], s[2 * t][3]);
            pa[t][2] = pack_f16(s[2 * t + 1][0], s[2 * t + 1][1]);
            pa[t][3] = pack_f16(s[2 * t + 1][2], s[2 * t + 1][3]);
        }

        CP_WAIT(0);
        __syncthreads();

#pragma unroll
        for (int t = 0; t < 4; ++t) {
#pragma unroll
            for (int g = 0; g < 8; ++g) {
                uint32_t vaddr = sb + FV + (t * 16 + rsel) * FSTRIDE +
                                 (g * 16 + ((lane >> 4) << 3)) * 2;
                uint32_t t0, t1, t2, t3;
                LDSM_X4_T(t0, t1, t2, t3, vaddr);
                uint32_t b0[2] = {t0, t1}, b1[2] = {t2, t3};
                MMA_F16(o_[2 * g], pa[t], b0);
                MMA_F16(o_[2 * g + 1], pa[t], b1);
            }
        }
    }

    // epilogue: normalize and emit single fp16 for the O projection
    const float inv0 = 1.f / l_[0];
    const float inv1 = 1.f / l_[1];
    const int r0g = qt * 128 + w * 16 + (lane >> 2);
#pragma unroll
    for (int nt = 0; nt < 16; ++nt) {
        int col = head * HD + nt * 8 + ((lane & 3) << 1);
        size_t o0 = (size_t)r0g * HID + col;
        size_t o1 = o0 + (size_t)8 * HID;
        *(__half2*)(g_aa + o0) = __floats2half2_rn(o_[nt][0] * inv0, o_[nt][1] * inv0);
        *(__half2*)(g_aa + o1) = __floats2half2_rn(o_[nt][2] * inv1, o_[nt][3] * inv1);
    }
}

// ---------------------------------------------------------------------------
// launch
// ---------------------------------------------------------------------------
extern "C" void kernel_launch(void* const* d_in, const int* in_sizes, int n_in,
                              void* d_out, int out_size) {
    const float* x = (const float*)d_in[0];
    const float* cosb = (const float*)d_in[1];
    const float* sinb = (const float*)d_in[2];
    // d_in[3] position_ids (arange; not dereferenced), d_in[4] seq_len
    const float* kc_in = (const float*)d_in[5];
    const float* vc_in = (const float*)d_in[6];
    const float* lnw = (const float*)d_in[7];
    const float* Wq = (const float*)d_in[8];
    const float* Wk = (const float*)d_in[9];
    const float* Wv = (const float*)d_in[10];
    const float* Wo = (const float*)d_in[11];

    float* out = (float*)d_out;
    float* kc_out = out + (size_t)L * HID;
    float* vc_out = kc_out + (size_t)MAXP * NKV * HD;

    __half *pHa, *pHl, *pW, *pAa;
    float *pQ, *pK, *pV;
    cudaGetSymbolAddress((void**)&pHa, g_ha);
    cudaGetSymbolAddress((void**)&pHl, g_hl);
    cudaGetSymbolAddress((void**)&pW, g_w);
    cudaGetSymbolAddress((void**)&pAa, g_aa);
    cudaGetSymbolAddress((void**)&pQ, g_q);
    cudaGetSymbolAddress((void**)&pK, g_k);
    cudaGetSymbolAddress((void**)&pV, g_v);

    copy_caches_kernel<<<(2 * (MAXP - L) * NKV * HD / 4) / 256, 256>>>(
        (const float4*)kc_in, (const float4*)vc_in, (float4*)kc_out, (float4*)vc_out);

    convert_all_kernel<<<(NW_TOTAL / 4) / 256, 256>>>(
        (const float4*)Wq, (const float4*)Wk, (const float4*)Wv, (const float4*)Wo, pW);

    rmsnorm_kernel<<<L, 256>>>(x, lnw);

    cudaFuncSetAttribute((const void*)mma_gemm_kernel<1, 2>,
                         cudaFuncAttributeMaxDynamicSharedMemorySize, GEMM_SMEM);
    cudaFuncSetAttribute((const void*)mma_gemm_kernel<2, 1>,
                         cudaFuncAttributeMaxDynamicSharedMemorySize, GEMM_SMEM);

    // fused Q+K+V projection: N = 6144, grid (24, 16), exact-pair A (2 terms)
    mma_gemm_kernel<1, 2><<<dim3(6144 / 256, L / 128), GTHREADS, GEMM_SMEM>>>(
        pHa, pHl, pW, pQ, pK, pV, 6144, nullptr);

    rope_q_kernel<<<(L * NH * 64) / 256, 256>>>(cosb, sinb);
    rope_kv_kernel<<<(L * NKV * 64) / 256, 256>>>(cosb, sinb, kc_out, vc_out);

    cudaFuncSetAttribute(flash_kernel, cudaFuncAttributeMaxDynamicSharedMemorySize, FLASH_SMEM);
    flash_kernel<<<dim3(L / 128, NH), 256, FLASH_SMEM>>>();

    // O projection with residual: single-fp16 A (1 term)
    mma_gemm_kernel<2, 1><<<dim3(HID / 256, L / 128), GTHREADS, GEMM_SMEM>>>(
        pAa, nullptr, pW + OFF_WO, out, nullptr, nullptr, HID, x);
}

// round 14
// speedup vs baseline: 2.6034x; 1.3955x over previous
#include <cuda_runtime.h>
#include <cuda_fp16.h>
#include <cstdint>

#define L 2048
#define HID 4096
#define NH 32
#define NKV 8
#define HD 128
#define MAXP 4096

// ---------------------------------------------------------------------------
// PTX helpers (sm_80-class instructions only: valid on baseline sm_103 target)
// ---------------------------------------------------------------------------
__device__ __forceinline__ uint32_t smem_u32(const void* p) {
    uint32_t a;
    asm("{ .reg .u64 t; cvta.to.shared.u64 t, %1; cvt.u32.u64 %0, t; }" : "=r"(a) : "l"(p));
    return a;
}
__device__ __forceinline__ float fast_exp2(float x) {
    float y;
    asm("ex2.approx.f32 %0, %1;" : "=f"(y) : "f"(x));
    return y;
}
#define LDSM_X4(r0, r1, r2, r3, addr)                                              \
    asm volatile("ldmatrix.sync.aligned.m8n8.x4.shared.b16 {%0,%1,%2,%3}, [%4];"   \
                 : "=r"(r0), "=r"(r1), "=r"(r2), "=r"(r3) : "r"(addr))
#define LDSM_X4_T(r0, r1, r2, r3, addr)                                            \
    asm volatile("ldmatrix.sync.aligned.m8n8.x4.trans.shared.b16 {%0,%1,%2,%3}, [%4];" \
                 : "=r"(r0), "=r"(r1), "=r"(r2), "=r"(r3) : "r"(addr))
#define MMA_F16(d, a, b)                                                           \
    asm volatile("mma.sync.aligned.m16n8k16.row.col.f32.f16.f16.f32 "              \
                 "{%0,%1,%2,%3}, {%4,%5,%6,%7}, {%8,%9}, {%0,%1,%2,%3};"           \
                 : "+f"((d)[0]), "+f"((d)[1]), "+f"((d)[2]), "+f"((d)[3])          \
                 : "r"((a)[0]), "r"((a)[1]), "r"((a)[2]), "r"((a)[3]),             \
                   "r"((b)[0]), "r"((b)[1]))
#define CP_ASYNC16(dst, src)                                                       \
    asm volatile("cp.async.cg.shared.global [%0], [%1], 16;" :: "r"(dst), "l"(src))
#define CP_COMMIT() asm volatile("cp.async.commit_group;" ::: "memory")
#define CP_WAIT(n) asm volatile("cp.async.wait_group %0;" :: "n"(n) : "memory")

// ---------------------------------------------------------------------------
// scratch (device globals; no runtime alloc)
// ---------------------------------------------------------------------------
#define NW_TOTAL 41943040
#define OFF_WQ 0
#define OFF_WK 16777216
#define OFF_WV 20971520
#define OFF_WO 25165824

__device__ __half g_ha[(size_t)L * HID];      // rmsnorm out, single fp16
__device__ __half g_w[(size_t)NW_TOTAL];      // all weights, single fp16
__device__ __half g_aa[(size_t)L * HID];      // attn out, single fp16
__device__ __half g_qh[(size_t)L * HID];      // roped+scaled Q, single fp16
__device__ __half g_kh[(size_t)L * NKV * HD]; // roped K, single fp16
__device__ __half g_vb[(size_t)L * NKV * HD]; // V, single fp16
__device__ float g_q[(size_t)L * HID];
__device__ float g_k[(size_t)L * NKV * HD];
__device__ float g_v[(size_t)L * NKV * HD];

__device__ __forceinline__ uint32_t pack_f16(float lo, float hi) {
    __half2 t = __floats2half2_rn(lo, hi);  // .x = lo bits [15:0]
    return *(uint32_t*)&t;
}

// ---------------------------------------------------------------------------
// cache copy — rows [L, MAXP) only (rope_kv fully writes rows [0, L))
// ---------------------------------------------------------------------------
__global__ void copy_caches_kernel(const float4* __restrict__ kin,
                                   const float4* __restrict__ vin,
                                   float4* __restrict__ kout,
                                   float4* __restrict__ vout) {
    int idx = blockIdx.x * 256 + threadIdx.x;
    const int n4 = (MAXP - L) * NKV * HD / 4;
    const int off = L * NKV * HD / 4;
    if (idx < n4) kout[off + idx] = kin[off + idx];
    else vout[off + idx - n4] = vin[off + idx - n4];
}

// ---------------------------------------------------------------------------
// fused weight convert: fp32 -> single fp16 (all 4 weights, one launch)
// ---------------------------------------------------------------------------
__global__ void convert_all_kernel(const float4* __restrict__ wq,
                                   const float4* __restrict__ wk,
                                   const float4* __restrict__ wv,
                                   const float4* __restrict__ wo,
                                   __half* __restrict__ w) {
    int i = blockIdx.x * 256 + threadIdx.x;  // [0, NW_TOTAL/4)
    const float4* src;
    int base;
    if (i < OFF_WK / 4) { src = wq; base = 0; }
    else if (i < OFF_WV / 4) { src = wk; base = OFF_WK / 4; }
    else if (i < OFF_WO / 4) { src = wv; base = OFF_WV / 4; }
    else { src = wo; base = OFF_WO / 4; }
    float4 v = src[i - base];
    __half2* hp = (__half2*)(w + (size_t)i * 4);
    hp[0] = __floats2half2_rn(v.x, v.y);
    hp[1] = __floats2half2_rn(v.z, v.w);
}

// ---------------------------------------------------------------------------
// RMSNorm -> single fp16
// ---------------------------------------------------------------------------
__global__ void __launch_bounds__(256) rmsnorm_kernel(const float* __restrict__ x,
                                                      const float* __restrict__ w) {
    int row = blockIdx.x;
    const float* xr = x + (size_t)row * HID;
    int t = threadIdx.x;
    float vals[16];
    float local = 0.f;
#pragma unroll
    for (int i = 0; i < 16; ++i) {
        float v = xr[t + i * 256];
        vals[i] = v;
        local += v * v;
    }
    __shared__ float red[8];
#pragma unroll
    for (int o = 16; o; o >>= 1) local += __shfl_xor_sync(0xffffffffu, local, o);
    if ((t & 31) == 0) red[t >> 5] = local;
    __syncthreads();
    if (t < 8) {
        float v = red[t];
#pragma unroll
        for (int o = 4; o; o >>= 1) v += __shfl_xor_sync(0xffu, v, o);
        if (t == 0) red[0] = v;
    }
    __syncthreads();
    float rms = rsqrtf(red[0] / (float)HID + 1e-5f);
    size_t base = (size_t)row * HID;
#pragma unroll
    for (int i = 0; i < 16; ++i) {
        float y = vals[i] * rms * w[t + i * 256];
        g_ha[base + t + i * 256] = __float2half_rn(y);
    }
}

// ---------------------------------------------------------------------------
// fp16 single-term GEMM: C = A B^T (+res). A, B single fp16.
// CTA 128x256, 512 threads (16 warps 4x4), warp tile 32x64, K-chunk 64,
// 2-stage cp.async. MAC-rate-bound path at the mma.sync floor.
// MODE 1: fused QKV (N=6144; route q/k/v).  MODE 2: +res.
// ---------------------------------------------------------------------------
#define GSTRIDE 144
#define ATILE 18432            // 128 * 144
#define BOFF  18432            // ATILE
#define BTILE 36864            // 256 * 144
#define GSTAGE 55296           // ATILE + BTILE
#define GEMM_SMEM (2 * GSTAGE) // 110592
#define GTHREADS 512

template <int MODE>
__global__ void __launch_bounds__(GTHREADS, 1) mma_gemm_kernel(
    const __half* __restrict__ A, const __half* __restrict__ B,
    float* __restrict__ C, float* __restrict__ Ck, float* __restrict__ Cvv,
    int N, const float* __restrict__ res) {
    extern __shared__ char sm[];
    const uint32_t sb = smem_u32(sm);
    const int tid = threadIdx.x;
    const int lane = tid & 31, w = tid >> 5;
    const int wm = w >> 2, wn = w & 3;          // 4 x 4 warps, warp tile 32x64
    const int bm = blockIdx.y * 128, bn = blockIdx.x * 256;

    float acc[2][8][4];
#pragma unroll
    for (int a = 0; a < 2; ++a)
#pragma unroll
        for (int b = 0; b < 8; ++b)
#pragma unroll
            for (int c = 0; c < 4; ++c) acc[a][b][c] = 0.f;

    auto issue = [&](int c, int s) {
#pragma unroll
        for (int j = 0; j < 2; ++j) {            // A: 1024 chunks
            const int local = tid + j * GTHREADS;
            const int row = local >> 3;
            const int seg = local & 7;
            const void* g = A + (size_t)(bm + row) * HID + c * 64 + seg * 8;
            uint32_t dst = sb + s * GSTAGE + row * GSTRIDE + seg * 16;
            CP_ASYNC16(dst, g);
        }
#pragma unroll
        for (int j = 0; j < 4; ++j) {            // B: 2048 chunks
            const int local = tid + j * GTHREADS;
            const int row = local >> 3;
            const int seg = local & 7;
            const void* g = B + (size_t)(bn + row) * HID + c * 64 + seg * 8;
            uint32_t dst = sb + s * GSTAGE + BOFF + row * GSTRIDE + seg * 16;
            CP_ASYNC16(dst, g);
        }
    };

    auto compute = [&](int s) {
        const uint32_t base = sb + s * GSTAGE;
        const int rsel = lane & 15;
        const int csel = (lane >> 4) << 4;
#pragma unroll
        for (int ks = 0; ks < 4; ++ks) {
            uint32_t a[2][4];
#pragma unroll
            for (int mt = 0; mt < 2; ++mt) {
                uint32_t ad = base + (wm * 32 + mt * 16 + rsel) * GSTRIDE + ks * 32 + csel;
                LDSM_X4(a[mt][0], a[mt][1], a[mt][2], a[mt][3], ad);
            }
#pragma unroll
            for (int half = 0; half < 2; ++half) {
                uint32_t b[4][2];
#pragma unroll
                for (int g = 0; g < 2; ++g) {
                    uint32_t bd = base + BOFF +
                                  (wn * 64 + (half * 2 + g) * 16 + rsel) * GSTRIDE +
                                  ks * 32 + csel;
                    uint32_t t0, t1, t2, t3;
                    LDSM_X4(t0, t1, t2, t3, bd);
                    b[2 * g][0] = t0; b[2 * g][1] = t2;
                    b[2 * g + 1][0] = t1; b[2 * g + 1][1] = t3;
                }
#pragma unroll
                for (int nt = 0; nt < 4; ++nt)
#pragma unroll
                    for (int mt = 0; mt < 2; ++mt)
                        MMA_F16(acc[mt][half * 4 + nt], a[mt], b[nt]);
            }
        }
    };

    issue(0, 0); CP_COMMIT();
    issue(1, 1); CP_COMMIT();
#pragma unroll 1
    for (int c = 0; c < 64; ++c) {
        if (c + 1 < 64) { CP_WAIT(1); } else { CP_WAIT(0); }
        __syncthreads();
        compute(c & 1);
        if (c + 2 < 64) {
            __syncthreads();
            issue(c + 2, c & 1);
            CP_COMMIT();
        }
    }

    // epilogue: route output
    float* Cout = C;
    int ncols = N, bnl = bn;
    if (MODE == 1) {
        if (bn < 4096) { Cout = C; ncols = 4096; bnl = bn; }
        else if (bn < 5120) { Cout = Ck; ncols = 1024; bnl = bn - 4096; }
        else { Cout = Cvv; ncols = 1024; bnl = bn - 5120; }
    }
#pragma unroll
    for (int mt = 0; mt < 2; ++mt)
#pragma unroll
        for (int nt = 0; nt < 8; ++nt) {
            int row = bm + wm * 32 + mt * 16 + (lane >> 2);
            int col = bnl + wn * 64 + nt * 8 + ((lane & 3) << 1);
            size_t o0 = (size_t)row * ncols + col;
            size_t o1 = (size_t)(row + 8) * ncols + col;
            float2 v0 = make_float2(acc[mt][nt][0], acc[mt][nt][1]);
            float2 v1 = make_float2(acc[mt][nt][2], acc[mt][nt][3]);
            if (MODE == 2) {
                float2 r0 = *(const float2*)&res[o0];
                float2 r1 = *(const float2*)&res[o1];
                v0.x += r0.x; v0.y += r0.y;
                v1.x += r1.x; v1.y += r1.y;
            }
            *(float2*)&Cout[o0] = v0;
            *(float2*)&Cout[o1] = v1;
        }
}

// ---------------------------------------------------------------------------
// RoPE Q: fp32 -> scaled (1/sqrt(hd) * log2e) single fp16
// ---------------------------------------------------------------------------
__global__ void rope_q_kernel(const float* __restrict__ cosb, const float* __restrict__ sinb) {
    const float QS = 0.08838834764831845f * 1.4426950408889634f;
    int idx = blockIdx.x * 256 + threadIdx.x;
    int d = idx & 63;
    int h = (idx >> 6) & (NH - 1);
    int i = idx >> 11;
    const float* qp = g_q + (size_t)i * HID + h * HD;
    float c0 = cosb[i * HD + d], s0 = sinb[i * HD + d];
    float c1 = cosb[i * HD + d + 64], s1 = sinb[i * HD + d + 64];
    float q0 = qp[d], q1 = qp[d + 64];
    size_t base = (size_t)i * HID + h * HD;
    g_qh[base + d] = __float2half_rn((q0 * c0 - q1 * s0) * QS);
    g_qh[base + d + 64] = __float2half_rn((q1 * c1 + q0 * s1) * QS);
}

// RoPE K + scatter fp32 caches + single fp16 K, fp16 V
__global__ void rope_kv_kernel(const float* __restrict__ cosb, const float* __restrict__ sinb,
                               float* __restrict__ kc_out, float* __restrict__ vc_out) {
    int idx = blockIdx.x * 256 + threadIdx.x;
    int d = idx & 63;
    int h = (idx >> 6) & (NKV - 1);
    int i = idx >> 9;
    size_t base = (size_t)i * (NKV * HD) + h * HD;
    float c0 = cosb[i * HD + d], s0 = sinb[i * HD + d];
    float c1 = cosb[i * HD + d + 64], s1 = sinb[i * HD + d + 64];
    float k0 = g_k[base + d], k1 = g_k[base + d + 64];
    float k0n = k0 * c0 - k1 * s0;
    float k1n = k1 * c1 + k0 * s1;
    kc_out[base + d] = k0n;
    kc_out[base + d + 64] = k1n;
    g_kh[base + d] = __float2half_rn(k0n);
    g_kh[base + d + 64] = __float2half_rn(k1n);
    float v0 = g_v[base + d], v1 = g_v[base + d + 64];
    vc_out[base + d] = v0;
    vc_out[base + d + 64] = v1;
    g_vb[base + d] = __float2half_rn(v0);
    g_vb[base + d + 64] = __float2half_rn(v1);
}

// ---------------------------------------------------------------------------
// Flash attention via fp16 mma: BM=128 (8 warps x m16), BN=64, HD=128.
// QK^T: single fp16 Q x single fp16 K = 1 mma term.
// softmax fp32 exp2 (scale folded into Q); P fp16; PV fp16 via ldmatrix.trans.
// Split cp.async waits: V load overlaps the whole S-phase.
// ---------------------------------------------------------------------------
#define FSTRIDE 272
#define FQH 0
#define FKH 34816
#define FV 52224
#define FLASH_SMEM 69632

__global__ void __launch_bounds__(256, 1) flash_kernel() {
    extern __shared__ char sm[];
    const uint32_t sb = smem_u32(sm);
    const int tid = threadIdx.x;
    const int lane = tid & 31, w = tid >> 5;
    const int qt = gridDim.x - 1 - blockIdx.x;  // heavy tiles first
    const int head = blockIdx.y;
    const int kvh = head >> 2;
    const int rsel = lane & 15;
    const int csel = (lane >> 4) << 4;

#pragma unroll
    for (int j = 0; j < 8; ++j) {
        const int local = tid + j * 256;
        const int row = local >> 4;
        const int seg = local & 15;
        const void* g = g_qh + (size_t)(qt * 128 + row) * HID + head * HD + seg * 8;
        uint32_t dst = sb + FQH + row * FSTRIDE + seg * 16;
        CP_ASYNC16(dst, g);
    }
    CP_COMMIT();

    float o_[16][4];
#pragma unroll
    for (int n = 0; n < 16; ++n)
#pragma unroll
        for (int c = 0; c < 4; ++c) o_[n][c] = 0.f;
    float m_[2] = {-1e30f, -1e30f};
    float l_[2] = {0.f, 0.f};

    const int kt_end = 2 * qt + 2;
#pragma unroll 1
    for (int kt = 0; kt < kt_end; ++kt) {
        __syncthreads();
        // K (group: K)
#pragma unroll
        for (int j = 0; j < 4; ++j) {
            const int local = tid + j * 256;
            const int row = local >> 4;
            const int seg = local & 15;
            const void* g = g_kh + (size_t)(kt * 64 + row) * (NKV * HD) + kvh * HD + seg * 8;
            uint32_t dst = sb + FKH + row * FSTRIDE + seg * 16;
            CP_ASYNC16(dst, g);
        }
        CP_COMMIT();
        // V (group: V) — overlaps the S phase below
#pragma unroll
        for (int j = 0; j < 4; ++j) {
            const int local = tid + j * 256;
            const int row = local >> 4;
            const int seg = local & 15;
            const void* g = g_vb + (size_t)(kt * 64 + row) * (NKV * HD) + kvh * HD + seg * 8;
            uint32_t dst = sb + FV + row * FSTRIDE + seg * 16;
            CP_ASYNC16(dst, g);
        }
        CP_COMMIT();

        CP_WAIT(1);
        __syncthreads();

        float s[8][4];
#pragma unroll
        for (int n = 0; n < 8; ++n)
#pragma unroll
            for (int c = 0; c < 4; ++c) s[n][c] = 0.f;
#pragma unroll
        for (int ks = 0; ks < 8; ++ks) {
            uint32_t a[4];
            uint32_t aaddr = sb + FQH + (w * 16 + rsel) * FSTRIDE + ks * 32 + csel;
            LDSM_X4(a[0], a[1], a[2], a[3], aaddr);
#pragma unroll
            for (int half = 0; half < 2; ++half) {
                uint32_t b[4][2];
#pragma unroll
                for (int g = 0; g < 2; ++g) {
                    uint32_t bd = sb + FKH +
                                  ((half * 2 + g) * 16 + rsel) * FSTRIDE + ks * 32 + csel;
                    uint32_t t0, t1, t2, t3;
                    LDSM_X4(t0, t1, t2, t3, bd);
                    b[2 * g][0] = t0; b[2 * g][1] = t2;
                    b[2 * g + 1][0] = t1; b[2 * g + 1][1] = t3;
                }
#pragma unroll
                for (int n = 0; n < 4; ++n) MMA_F16(s[half * 4 + n], a, b[n]);
            }
        }

        if (kt >= 2 * qt) {
            const int r0g = qt * 128 + w * 16 + (lane >> 2);
#pragma unroll
            for (int j = 0; j < 8; ++j) {
                int cb = kt * 64 + j * 8 + ((lane & 3) << 1);
                if (cb > r0g) s[j][0] = -1e30f;
                if (cb + 1 > r0g) s[j][1] = -1e30f;
                if (cb > r0g + 8) s[j][2] = -1e30f;
                if (cb + 1 > r0g + 8) s[j][3] = -1e30f;
            }
        }

#pragma unroll
        for (int i = 0; i < 2; ++i) {
            float mt_ = -1e30f;
#pragma unroll
            for (int j = 0; j < 8; ++j)
                mt_ = fmaxf(mt_, fmaxf(s[j][2 * i], s[j][2 * i + 1]));
            mt_ = fmaxf(mt_, __shfl_xor_sync(0xffffffffu, mt_, 1));
            mt_ = fmaxf(mt_, __shfl_xor_sync(0xffffffffu, mt_, 2));
            float mn = fmaxf(m_[i], mt_);
            float corr = fast_exp2(m_[i] - mn);
            m_[i] = mn;
            float rs = 0.f;
#pragma unroll
            for (int j = 0; j < 8; ++j) {
                float p0 = fast_exp2(s[j][2 * i] - mn);
                float p1 = fast_exp2(s[j][2 * i + 1] - mn);
                s[j][2 * i] = p0;
                s[j][2 * i + 1] = p1;
                rs += p0 + p1;
            }
            rs += __shfl_xor_sync(0xffffffffu, rs, 1);
            rs += __shfl_xor_sync(0xffffffffu, rs, 2);
            l_[i] = l_[i] * corr + rs;
#pragma unroll
            for (int n = 0; n < 16; ++n) {
                o_[n][2 * i] *= corr;
                o_[n][2 * i + 1] *= corr;
            }
        }

        uint32_t pa[4][4];
#pragma unroll
        for (int t = 0; t < 4; ++t) {
            pa[t][0] = pack_f16(s[2 * t][0], s[2 * t][1]);
            pa[t][1] = pack_f16(s[2 * t][2], s[2 * t][3]);
            pa[t][2] = pack_f16(s[2 * t + 1][0], s[2 * t + 1][1]);
            pa[t][3] = pack_f16(s[2 * t + 1][2], s[2 * t + 1][3]);
        }

        CP_WAIT(0);
        __syncthreads();

#pragma unroll
        for (int t = 0; t < 4; ++t) {
#pragma unroll
            for (int g = 0; g < 8; ++g) {
                uint32_t vaddr = sb + FV + (t * 16 + rsel) * FSTRIDE +
                                 (g * 16 + ((lane >> 4) << 3)) * 2;
                uint32_t t0, t1, t2, t3;
                LDSM_X4_T(t0, t1, t2, t3, vaddr);
                uint32_t b0[2] = {t0, t1}, b1[2] = {t2, t3};
                MMA_F16(o_[2 * g], pa[t], b0);
                MMA_F16(o_[2 * g + 1], pa[t], b1);
            }
        }
    }

    // epilogue: normalize and emit single fp16 for the O projection
    const float inv0 = 1.f / l_[0];
    const float inv1 = 1.f / l_[1];
    const int r0g = qt * 128 + w * 16 + (lane >> 2);
#pragma unroll
    for (int nt = 0; nt < 16; ++nt) {
        int col = head * HD + nt * 8 + ((lane & 3) << 1);
        size_t o0 = (size_t)r0g * HID + col;
        size_t o1 = o0 + (size_t)8 * HID;
        *(__half2*)(g_aa + o0) = __floats2half2_rn(o_[nt][0] * inv0, o_[nt][1] * inv0);
        *(__half2*)(g_aa + o1) = __floats2half2_rn(o_[nt][2] * inv1, o_[nt][3] * inv1);
    }
}

// ---------------------------------------------------------------------------
// launch
// ---------------------------------------------------------------------------
extern "C" void kernel_launch(void* const* d_in, const int* in_sizes, int n_in,
                              void* d_out, int out_size) {
    const float* x = (const float*)d_in[0];
    const float* cosb = (const float*)d_in[1];
    const float* sinb = (const float*)d_in[2];
    // d_in[3] position_ids (arange; not dereferenced), d_in[4] seq_len
    const float* kc_in = (const float*)d_in[5];
    const float* vc_in = (const float*)d_in[6];
    const float* lnw = (const float*)d_in[7];
    const float* Wq = (const float*)d_in[8];
    const float* Wk = (const float*)d_in[9];
    const float* Wv = (const float*)d_in[10];
    const float* Wo = (const float*)d_in[11];

    float* out = (float*)d_out;
    float* kc_out = out + (size_t)L * HID;
    float* vc_out = kc_out + (size_t)MAXP * NKV * HD;

    __half *pHa, *pW, *pAa;
    float *pQ, *pK, *pV;
    cudaGetSymbolAddress((void**)&pHa, g_ha);
    cudaGetSymbolAddress((void**)&pW, g_w);
    cudaGetSymbolAddress((void**)&pAa, g_aa);
    cudaGetSymbolAddress((void**)&pQ, g_q);
    cudaGetSymbolAddress((void**)&pK, g_k);
    cudaGetSymbolAddress((void**)&pV, g_v);

    copy_caches_kernel<<<(2 * (MAXP - L) * NKV * HD / 4) / 256, 256>>>(
        (const float4*)kc_in, (const float4*)vc_in, (float4*)kc_out, (float4*)vc_out);

    convert_all_kernel<<<(NW_TOTAL / 4) / 256, 256>>>(
        (const float4*)Wq, (const float4*)Wk, (const float4*)Wv, (const float4*)Wo, pW);

    rmsnorm_kernel<<<L, 256>>>(x, lnw);

    cudaFuncSetAttribute((const void*)mma_gemm_kernel<1>,
                         cudaFuncAttributeMaxDynamicSharedMemorySize, GEMM_SMEM);
    cudaFuncSetAttribute((const void*)mma_gemm_kernel<2>,
                         cudaFuncAttributeMaxDynamicSharedMemorySize, GEMM_SMEM);

    // fused Q+K+V projection: N = 6144, grid (24, 16)
    mma_gemm_kernel<1><<<dim3(6144 / 256, L / 128), GTHREADS, GEMM_SMEM>>>(
        pHa, pW, pQ, pK, pV, 6144, nullptr);

    rope_q_kernel<<<(L * NH * 64) / 256, 256>>>(cosb, sinb);
    rope_kv_kernel<<<(L * NKV * 64) / 256, 256>>>(cosb, sinb, kc_out, vc_out);

    cudaFuncSetAttribute(flash_kernel, cudaFuncAttributeMaxDynamicSharedMemorySize, FLASH_SMEM);
    flash_kernel<<<dim3(L / 128, NH), 256, FLASH_SMEM>>>();

    // O projection with residual
    mma_gemm_kernel<2><<<dim3(HID / 256, L / 128), GTHREADS, GEMM_SMEM>>>(
        pAa, pW + OFF_WO, out, nullptr, nullptr, HID, x);
}

// round 15
// speedup vs baseline: 2.6062x; 1.0011x over previous
#include <cuda_runtime.h>
#include <cuda_fp16.h>
#include <cstdint>

#define L 2048
#define HID 4096
#define NH 32
#define NKV 8
#define HD 128
#define MAXP 4096

// ---------------------------------------------------------------------------
// PTX helpers (sm_80-class instructions only: valid on baseline sm_103 target)
// ---------------------------------------------------------------------------
__device__ __forceinline__ uint32_t smem_u32(const void* p) {
    uint32_t a;
    asm("{ .reg .u64 t; cvta.to.shared.u64 t, %1; cvt.u32.u64 %0, t; }" : "=r"(a) : "l"(p));
    return a;
}
__device__ __forceinline__ float fast_exp2(float x) {
    float y;
    asm("ex2.approx.f32 %0, %1;" : "=f"(y) : "f"(x));
    return y;
}
#define LDSM_X4(r0, r1, r2, r3, addr)                                              \
    asm volatile("ldmatrix.sync.aligned.m8n8.x4.shared.b16 {%0,%1,%2,%3}, [%4];"   \
                 : "=r"(r0), "=r"(r1), "=r"(r2), "=r"(r3) : "r"(addr))
#define LDSM_X4_T(r0, r1, r2, r3, addr)                                            \
    asm volatile("ldmatrix.sync.aligned.m8n8.x4.trans.shared.b16 {%0,%1,%2,%3}, [%4];" \
                 : "=r"(r0), "=r"(r1), "=r"(r2), "=r"(r3) : "r"(addr))
#define MMA_F16(d, a, b)                                                           \
    asm volatile("mma.sync.aligned.m16n8k16.row.col.f32.f16.f16.f32 "              \
                 "{%0,%1,%2,%3}, {%4,%5,%6,%7}, {%8,%9}, {%0,%1,%2,%3};"           \
                 : "+f"((d)[0]), "+f"((d)[1]), "+f"((d)[2]), "+f"((d)[3])          \
                 : "r"((a)[0]), "r"((a)[1]), "r"((a)[2]), "r"((a)[3]),             \
                   "r"((b)[0]), "r"((b)[1]))
#define CP_ASYNC16(dst, src)                                                       \
    asm volatile("cp.async.cg.shared.global [%0], [%1], 16;" :: "r"(dst), "l"(src))
#define CP_COMMIT() asm volatile("cp.async.commit_group;" ::: "memory")
#define CP_WAIT(n) asm volatile("cp.async.wait_group %0;" :: "n"(n) : "memory")

// ---------------------------------------------------------------------------
// scratch (device globals; no runtime alloc)
// ---------------------------------------------------------------------------
#define NW_TOTAL 41943040
#define OFF_WQ 0
#define OFF_WK 16777216
#define OFF_WV 20971520
#define OFF_WO 25165824

__device__ __half g_ha[(size_t)L * HID];      // rmsnorm out, single fp16
__device__ __half g_w[(size_t)NW_TOTAL];      // all weights, single fp16
__device__ __half g_aa[(size_t)L * HID];      // attn out, single fp16
__device__ __half g_qh[(size_t)L * HID];      // roped+scaled Q, single fp16
__device__ __half g_kh[(size_t)L * NKV * HD]; // roped K, single fp16
__device__ __half g_vb[(size_t)L * NKV * HD]; // V, single fp16
__device__ float g_q[(size_t)L * HID];
__device__ float g_k[(size_t)L * NKV * HD];
__device__ float g_v[(size_t)L * NKV * HD];

__device__ __forceinline__ uint32_t pack_f16(float lo, float hi) {
    __half2 t = __floats2half2_rn(lo, hi);  // .x = lo bits [15:0]
    return *(uint32_t*)&t;
}

// ---------------------------------------------------------------------------
// cache copy — rows [L, MAXP) only (rope_kv fully writes rows [0, L))
// ---------------------------------------------------------------------------
__global__ void copy_caches_kernel(const float4* __restrict__ kin,
                                   const float4* __restrict__ vin,
                                   float4* __restrict__ kout,
                                   float4* __restrict__ vout) {
    int idx = blockIdx.x * 256 + threadIdx.x;
    const int n4 = (MAXP - L) * NKV * HD / 4;
    const int off = L * NKV * HD / 4;
    if (idx < n4) kout[off + idx] = kin[off + idx];
    else vout[off + idx - n4] = vin[off + idx - n4];
}

// ---------------------------------------------------------------------------
// fused weight convert: fp32 -> single fp16 (all 4 weights, one launch)
// ---------------------------------------------------------------------------
__global__ void convert_all_kernel(const float4* __restrict__ wq,
                                   const float4* __restrict__ wk,
                                   const float4* __restrict__ wv,
                                   const float4* __restrict__ wo,
                                   __half* __restrict__ w) {
    int i = blockIdx.x * 256 + threadIdx.x;  // [0, NW_TOTAL/4)
    const float4* src;
    int base;
    if (i < OFF_WK / 4) { src = wq; base = 0; }
    else if (i < OFF_WV / 4) { src = wk; base = OFF_WK / 4; }
    else if (i < OFF_WO / 4) { src = wv; base = OFF_WV / 4; }
    else { src = wo; base = OFF_WO / 4; }
    float4 v = src[i - base];
    __half2* hp = (__half2*)(w + (size_t)i * 4);
    hp[0] = __floats2half2_rn(v.x, v.y);
    hp[1] = __floats2half2_rn(v.z, v.w);
}

// ---------------------------------------------------------------------------
// RMSNorm -> single fp16
// ---------------------------------------------------------------------------
__global__ void __launch_bounds__(256) rmsnorm_kernel(const float* __restrict__ x,
                                                      const float* __restrict__ w) {
    int row = blockIdx.x;
    const float* xr = x + (size_t)row * HID;
    int t = threadIdx.x;
    float vals[16];
    float local = 0.f;
#pragma unroll
    for (int i = 0; i < 16; ++i) {
        float v = xr[t + i * 256];
        vals[i] = v;
        local += v * v;
    }
    __shared__ float red[8];
#pragma unroll
    for (int o = 16; o; o >>= 1) local += __shfl_xor_sync(0xffffffffu, local, o);
    if ((t & 31) == 0) red[t >> 5] = local;
    __syncthreads();
    if (t < 8) {
        float v = red[t];
#pragma unroll
        for (int o = 4; o; o >>= 1) v += __shfl_xor_sync(0xffu, v, o);
        if (t == 0) red[0] = v;
    }
    __syncthreads();
    float rms = rsqrtf(red[0] / (float)HID + 1e-5f);
    size_t base = (size_t)row * HID;
#pragma unroll
    for (int i = 0; i < 16; ++i) {
        float y = vals[i] * rms * w[t + i * 256];
        g_ha[base + t + i * 256] = __float2half_rn(y);
    }
}

// ---------------------------------------------------------------------------
// fp16 single-term GEMM: C = A B^T (+res). A, B single fp16.
// CTA 128x256, 512 threads (16 warps 4x4), warp tile 32x64, K-chunk 64,
// 2-stage cp.async. At the mma.sync MAC-rate floor (~512 MACs/cyc/SM).
// MODE 1: fused QKV (N=6144; route q/k/v).  MODE 2: +res.
// ---------------------------------------------------------------------------
#define GSTRIDE 144
#define ATILE 18432            // 128 * 144
#define BOFF  18432            // ATILE
#define BTILE 36864            // 256 * 144
#define GSTAGE 55296           // ATILE + BTILE
#define GEMM_SMEM (2 * GSTAGE) // 110592
#define GTHREADS 512

template <int MODE>
__global__ void __launch_bounds__(GTHREADS, 1) mma_gemm_kernel(
    const __half* __restrict__ A, const __half* __restrict__ B,
    float* __restrict__ C, float* __restrict__ Ck, float* __restrict__ Cvv,
    int N, const float* __restrict__ res) {
    extern __shared__ char sm[];
    const uint32_t sb = smem_u32(sm);
    const int tid = threadIdx.x;
    const int lane = tid & 31, w = tid >> 5;
    const int wm = w >> 2, wn = w & 3;          // 4 x 4 warps, warp tile 32x64
    const int bm = blockIdx.y * 128, bn = blockIdx.x * 256;

    float acc[2][8][4];
#pragma unroll
    for (int a = 0; a < 2; ++a)
#pragma unroll
        for (int b = 0; b < 8; ++b)
#pragma unroll
            for (int c = 0; c < 4; ++c) acc[a][b][c] = 0.f;

    auto issue = [&](int c, int s) {
#pragma unroll
        for (int j = 0; j < 2; ++j) {            // A: 1024 chunks
            const int local = tid + j * GTHREADS;
            const int row = local >> 3;
            const int seg = local & 7;
            const void* g = A + (size_t)(bm + row) * HID + c * 64 + seg * 8;
            uint32_t dst = sb + s * GSTAGE + row * GSTRIDE + seg * 16;
            CP_ASYNC16(dst, g);
        }
#pragma unroll
        for (int j = 0; j < 4; ++j) {            // B: 2048 chunks
            const int local = tid + j * GTHREADS;
            const int row = local >> 3;
            const int seg = local & 7;
            const void* g = B + (size_t)(bn + row) * HID + c * 64 + seg * 8;
            uint32_t dst = sb + s * GSTAGE + BOFF + row * GSTRIDE + seg * 16;
            CP_ASYNC16(dst, g);
        }
    };

    auto compute = [&](int s) {
        const uint32_t base = sb + s * GSTAGE;
        const int rsel = lane & 15;
        const int csel = (lane >> 4) << 4;
#pragma unroll
        for (int ks = 0; ks < 4; ++ks) {
            uint32_t a[2][4];
#pragma unroll
            for (int mt = 0; mt < 2; ++mt) {
                uint32_t ad = base + (wm * 32 + mt * 16 + rsel) * GSTRIDE + ks * 32 + csel;
                LDSM_X4(a[mt][0], a[mt][1], a[mt][2], a[mt][3], ad);
            }
#pragma unroll
            for (int half = 0; half < 2; ++half) {
                uint32_t b[4][2];
#pragma unroll
                for (int g = 0; g < 2; ++g) {
                    uint32_t bd = base + BOFF +
                                  (wn * 64 + (half * 2 + g) * 16 + rsel) * GSTRIDE +
                                  ks * 32 + csel;
                    uint32_t t0, t1, t2, t3;
                    LDSM_X4(t0, t1, t2, t3, bd);
                    b[2 * g][0] = t0; b[2 * g][1] = t2;
                    b[2 * g + 1][0] = t1; b[2 * g + 1][1] = t3;
                }
#pragma unroll
                for (int nt = 0; nt < 4; ++nt)
#pragma unroll
                    for (int mt = 0; mt < 2; ++mt)
                        MMA_F16(acc[mt][half * 4 + nt], a[mt], b[nt]);
            }
        }
    };

    issue(0, 0); CP_COMMIT();
    issue(1, 1); CP_COMMIT();
#pragma unroll 1
    for (int c = 0; c < 64; ++c) {
        if (c + 1 < 64) { CP_WAIT(1); } else { CP_WAIT(0); }
        __syncthreads();
        compute(c & 1);
        if (c + 2 < 64) {
            __syncthreads();
            issue(c + 2, c & 1);
            CP_COMMIT();
        }
    }

    // epilogue: route output
    float* Cout = C;
    int ncols = N, bnl = bn;
    if (MODE == 1) {
        if (bn < 4096) { Cout = C; ncols = 4096; bnl = bn; }
        else if (bn < 5120) { Cout = Ck; ncols = 1024; bnl = bn - 4096; }
        else { Cout = Cvv; ncols = 1024; bnl = bn - 5120; }
    }
#pragma unroll
    for (int mt = 0; mt < 2; ++mt)
#pragma unroll
        for (int nt = 0; nt < 8; ++nt) {
            int row = bm + wm * 32 + mt * 16 + (lane >> 2);
            int col = bnl + wn * 64 + nt * 8 + ((lane & 3) << 1);
            size_t o0 = (size_t)row * ncols + col;
            size_t o1 = (size_t)(row + 8) * ncols + col;
            float2 v0 = make_float2(acc[mt][nt][0], acc[mt][nt][1]);
            float2 v1 = make_float2(acc[mt][nt][2], acc[mt][nt][3]);
            if (MODE == 2) {
                float2 r0 = *(const float2*)&res[o0];
                float2 r1 = *(const float2*)&res[o1];
                v0.x += r0.x; v0.y += r0.y;
                v1.x += r1.x; v1.y += r1.y;
            }
            *(float2*)&Cout[o0] = v0;
            *(float2*)&Cout[o1] = v1;
        }
}

// ---------------------------------------------------------------------------
// fused RoPE: Q (scaled fp16) + K (fp16 + fp32 cache) + V passthrough
// idx < L*NH*64: Q element pair; else: KV element pair.
// ---------------------------------------------------------------------------
#define QTOTAL (L * NH * 64)
#define KVTOTAL (L * NKV * 64)
__global__ void rope_all_kernel(const float* __restrict__ cosb, const float* __restrict__ sinb,
                                float* __restrict__ kc_out, float* __restrict__ vc_out) {
    const float QS = 0.08838834764831845f * 1.4426950408889634f;
    int idx = blockIdx.x * 256 + threadIdx.x;
    if (idx < QTOTAL) {
        int d = idx & 63;
        int h = (idx >> 6) & (NH - 1);
        int i = idx >> 11;
        const float* qp = g_q + (size_t)i * HID + h * HD;
        float c0 = cosb[i * HD + d], s0 = sinb[i * HD + d];
        float c1 = cosb[i * HD + d + 64], s1 = sinb[i * HD + d + 64];
        float q0 = qp[d], q1 = qp[d + 64];
        size_t base = (size_t)i * HID + h * HD;
        g_qh[base + d] = __float2half_rn((q0 * c0 - q1 * s0) * QS);
        g_qh[base + d + 64] = __float2half_rn((q1 * c1 + q0 * s1) * QS);
    } else {
        idx -= QTOTAL;
        int d = idx & 63;
        int h = (idx >> 6) & (NKV - 1);
        int i = idx >> 9;
        size_t base = (size_t)i * (NKV * HD) + h * HD;
        float c0 = cosb[i * HD + d], s0 = sinb[i * HD + d];
        float c1 = cosb[i * HD + d + 64], s1 = sinb[i * HD + d + 64];
        float k0 = g_k[base + d], k1 = g_k[base + d + 64];
        float k0n = k0 * c0 - k1 * s0;
        float k1n = k1 * c1 + k0 * s1;
        kc_out[base + d] = k0n;
        kc_out[base + d + 64] = k1n;
        g_kh[base + d] = __float2half_rn(k0n);
        g_kh[base + d + 64] = __float2half_rn(k1n);
        float v0 = g_v[base + d], v1 = g_v[base + d + 64];
        vc_out[base + d] = v0;
        vc_out[base + d + 64] = v1;
        g_vb[base + d] = __float2half_rn(v0);
        g_vb[base + d + 64] = __float2half_rn(v1);
    }
}

// ---------------------------------------------------------------------------
// Flash attention via fp16 mma: BM=128 (8 warps x m16), BN=64, HD=128.
// Double-buffered K/V with cross-iteration prefetch: at each iteration the
// kt+1 tile loads issue immediately after waiting on kt's, hiding the full
// load latency under S+softmax+PV. 2 CTAs/SM (smem 104448 x2 = 209KB).
// ---------------------------------------------------------------------------
#define FSTRIDE 272
#define FQ 0
#define FK0 34816
#define FK1 52224
#define FV0 69632
#define FV1 87040
#define FLASH_SMEM 104448

__global__ void __launch_bounds__(256, 2) flash_kernel() {
    extern __shared__ char sm[];
    const uint32_t sb = smem_u32(sm);
    const int tid = threadIdx.x;
    const int lane = tid & 31, w = tid >> 5;
    const int qt = gridDim.x - 1 - blockIdx.x;  // heavy tiles first
    const int head = blockIdx.y;
    const int kvh = head >> 2;
    const int rsel = lane & 15;
    const int csel = (lane >> 4) << 4;

    auto issue_kv = [&](int kt, int s) {
        const uint32_t kb = sb + (s ? FK1 : FK0);
        const uint32_t vb = sb + (s ? FV1 : FV0);
#pragma unroll
        for (int j = 0; j < 4; ++j) {
            const int local = tid + j * 256;
            const int row = local >> 4;
            const int seg = local & 15;
            size_t goff = (size_t)(kt * 64 + row) * (NKV * HD) + kvh * HD + seg * 8;
            CP_ASYNC16(kb + row * FSTRIDE + seg * 16, g_kh + goff);
        }
#pragma unroll
        for (int j = 0; j < 4; ++j) {
            const int local = tid + j * 256;
            const int row = local >> 4;
            const int seg = local & 15;
            size_t goff = (size_t)(kt * 64 + row) * (NKV * HD) + kvh * HD + seg * 8;
            CP_ASYNC16(vb + row * FSTRIDE + seg * 16, g_vb + goff);
        }
    };

    // Q tile
#pragma unroll
    for (int j = 0; j < 8; ++j) {
        const int local = tid + j * 256;
        const int row = local >> 4;
        const int seg = local & 15;
        const void* g = g_qh + (size_t)(qt * 128 + row) * HID + head * HD + seg * 8;
        CP_ASYNC16(sb + FQ + row * FSTRIDE + seg * 16, g);
    }
    issue_kv(0, 0);
    CP_COMMIT();

    float o_[16][4];
#pragma unroll
    for (int n = 0; n < 16; ++n)
#pragma unroll
        for (int c = 0; c < 4; ++c) o_[n][c] = 0.f;
    float m_[2] = {-1e30f, -1e30f};
    float l_[2] = {0.f, 0.f};

    const int kt_end = 2 * qt + 2;
#pragma unroll 1
    for (int kt = 0; kt < kt_end; ++kt) {
        const int s = kt & 1;
        CP_WAIT(0);       // tile kt (prefetched last iteration) resident
        __syncthreads();  // visible to all warps; prior buffer fully consumed
        if (kt + 1 < kt_end) {
            issue_kv(kt + 1, s ^ 1);
            CP_COMMIT();
        }
        const uint32_t kb = sb + (s ? FK1 : FK0);
        const uint32_t vb = sb + (s ? FV1 : FV0);

        float sc[8][4];
#pragma unroll
        for (int n = 0; n < 8; ++n)
#pragma unroll
            for (int c = 0; c < 4; ++c) sc[n][c] = 0.f;
#pragma unroll
        for (int ks = 0; ks < 8; ++ks) {
            uint32_t a[4];
            uint32_t aaddr = sb + FQ + (w * 16 + rsel) * FSTRIDE + ks * 32 + csel;
            LDSM_X4(a[0], a[1], a[2], a[3], aaddr);
#pragma unroll
            for (int half = 0; half < 2; ++half) {
                uint32_t b[4][2];
#pragma unroll
                for (int g = 0; g < 2; ++g) {
                    uint32_t bd = kb + ((half * 2 + g) * 16 + rsel) * FSTRIDE + ks * 32 + csel;
                    uint32_t t0, t1, t2, t3;
                    LDSM_X4(t0, t1, t2, t3, bd);
                    b[2 * g][0] = t0; b[2 * g][1] = t2;
                    b[2 * g + 1][0] = t1; b[2 * g + 1][1] = t3;
                }
#pragma unroll
                for (int n = 0; n < 4; ++n) MMA_F16(sc[half * 4 + n], a, b[n]);
            }
        }

        if (kt >= 2 * qt) {
            const int r0g = qt * 128 + w * 16 + (lane >> 2);
#pragma unroll
            for (int j = 0; j < 8; ++j) {
                int cb = kt * 64 + j * 8 + ((lane & 3) << 1);
                if (cb > r0g) sc[j][0] = -1e30f;
                if (cb + 1 > r0g) sc[j][1] = -1e30f;
                if (cb > r0g + 8) sc[j][2] = -1e30f;
                if (cb + 1 > r0g + 8) sc[j][3] = -1e30f;
            }
        }

#pragma unroll
        for (int i = 0; i < 2; ++i) {
            float mt_ = -1e30f;
#pragma unroll
            for (int j = 0; j < 8; ++j)
                mt_ = fmaxf(mt_, fmaxf(sc[j][2 * i], sc[j][2 * i + 1]));
            mt_ = fmaxf(mt_, __shfl_xor_sync(0xffffffffu, mt_, 1));
            mt_ = fmaxf(mt_, __shfl_xor_sync(0xffffffffu, mt_, 2));
            float mn = fmaxf(m_[i], mt_);
            float corr = fast_exp2(m_[i] - mn);
            m_[i] = mn;
            float rs = 0.f;
#pragma unroll
            for (int j = 0; j < 8; ++j) {
                float p0 = fast_exp2(sc[j][2 * i] - mn);
                float p1 = fast_exp2(sc[j][2 * i + 1] - mn);
                sc[j][2 * i] = p0;
                sc[j][2 * i + 1] = p1;
                rs += p0 + p1;
            }
            rs += __shfl_xor_sync(0xffffffffu, rs, 1);
            rs += __shfl_xor_sync(0xffffffffu, rs, 2);
            l_[i] = l_[i] * corr + rs;
#pragma unroll
            for (int n = 0; n < 16; ++n) {
                o_[n][2 * i] *= corr;
                o_[n][2 * i + 1] *= corr;
            }
        }

        uint32_t pa[4][4];
#pragma unroll
        for (int t = 0; t < 4; ++t) {
            pa[t][0] = pack_f16(sc[2 * t][0], sc[2 * t][1]);
            pa[t][1] = pack_f16(sc[2 * t][2], sc[2 * t][3]);
            pa[t][2] = pack_f16(sc[2 * t + 1][0], sc[2 * t + 1][1]);
            pa[t][3] = pack_f16(sc[2 * t + 1][2], sc[2 * t + 1][3]);
        }

#pragma unroll
        for (int t = 0; t < 4; ++t) {
#pragma unroll
            for (int g = 0; g < 8; ++g) {
                uint32_t vaddr = vb + (t * 16 + rsel) * FSTRIDE +
                                 (g * 16 + ((lane >> 4) << 3)) * 2;
                uint32_t t0, t1, t2, t3;
                LDSM_X4_T(t0, t1, t2, t3, vaddr);
                uint32_t b0[2] = {t0, t1}, b1[2] = {t2, t3};
                MMA_F16(o_[2 * g], pa[t], b0);
                MMA_F16(o_[2 * g + 1], pa[t], b1);
            }
        }
    }

    // epilogue: normalize and emit single fp16 for the O projection
    const float inv0 = 1.f / l_[0];
    const float inv1 = 1.f / l_[1];
    const int r0g = qt * 128 + w * 16 + (lane >> 2);
#pragma unroll
    for (int nt = 0; nt < 16; ++nt) {
        int col = head * HD + nt * 8 + ((lane & 3) << 1);
        size_t o0 = (size_t)r0g * HID + col;
        size_t o1 = o0 + (size_t)8 * HID;
        *(__half2*)(g_aa + o0) = __floats2half2_rn(o_[nt][0] * inv0, o_[nt][1] * inv0);
        *(__half2*)(g_aa + o1) = __floats2half2_rn(o_[nt][2] * inv1, o_[nt][3] * inv1);
    }
}

// ---------------------------------------------------------------------------
// launch
// ---------------------------------------------------------------------------
extern "C" void kernel_launch(void* const* d_in, const int* in_sizes, int n_in,
                              void* d_out, int out_size) {
    const float* x = (const float*)d_in[0];
    const float* cosb = (const float*)d_in[1];
    const float* sinb = (const float*)d_in[2];
    // d_in[3] position_ids (arange; not dereferenced), d_in[4] seq_len
    const float* kc_in = (const float*)d_in[5];
    const float* vc_in = (const float*)d_in[6];
    const float* lnw = (const float*)d_in[7];
    const float* Wq = (const float*)d_in[8];
    const float* Wk = (const float*)d_in[9];
    const float* Wv = (const float*)d_in[10];
    const float* Wo = (const float*)d_in[11];

    float* out = (float*)d_out;
    float* kc_out = out + (size_t)L * HID;
    float* vc_out = kc_out + (size_t)MAXP * NKV * HD;

    __half *pHa, *pW, *pAa;
    float *pQ, *pK, *pV;
    cudaGetSymbolAddress((void**)&pHa, g_ha);
    cudaGetSymbolAddress((void**)&pW, g_w);
    cudaGetSymbolAddress((void**)&pAa, g_aa);
    cudaGetSymbolAddress((void**)&pQ, g_q);
    cudaGetSymbolAddress((void**)&pK, g_k);
    cudaGetSymbolAddress((void**)&pV, g_v);

    copy_caches_kernel<<<(2 * (MAXP - L) * NKV * HD / 4) / 256, 256>>>(
        (const float4*)kc_in, (const float4*)vc_in, (float4*)kc_out, (float4*)vc_out);

    convert_all_kernel<<<(NW_TOTAL / 4) / 256, 256>>>(
        (const float4*)Wq, (const float4*)Wk, (const float4*)Wv, (const float4*)Wo, pW);

    rmsnorm_kernel<<<L, 256>>>(x, lnw);

    cudaFuncSetAttribute((const void*)mma_gemm_kernel<1>,
                         cudaFuncAttributeMaxDynamicSharedMemorySize, GEMM_SMEM);
    cudaFuncSetAttribute((const void*)mma_gemm_kernel<2>,
                         cudaFuncAttributeMaxDynamicSharedMemorySize, GEMM_SMEM);

    // fused Q+K+V projection: N = 6144, grid (24, 16)
    mma_gemm_kernel<1><<<dim3(6144 / 256, L / 128), GTHREADS, GEMM_SMEM>>>(
        pHa, pW, pQ, pK, pV, 6144, nullptr);

    rope_all_kernel<<<(QTOTAL + KVTOTAL) / 256, 256>>>(cosb, sinb, kc_out, vc_out);

    cudaFuncSetAttribute(flash_kernel, cudaFuncAttributeMaxDynamicSharedMemorySize, FLASH_SMEM);
    flash_kernel<<<dim3(L / 128, NH), 256, FLASH_SMEM>>>();

    // O projection with residual
    mma_gemm_kernel<2><<<dim3(HID / 256, L / 128), GTHREADS, GEMM_SMEM>>>(
        pAa, pW + OFF_WO, out, nullptr, nullptr, HID, x);
}

// round 16
// speedup vs baseline: 2.6293x; 1.0089x over previous
#include <cuda_runtime.h>
#include <cuda_fp16.h>
#include <cstdint>

#define L 2048
#define HID 4096
#define NH 32
#define NKV 8
#define HD 128
#define MAXP 4096

// ---------------------------------------------------------------------------
// PTX helpers (sm_80-class instructions only: valid on baseline sm_103 target)
// ---------------------------------------------------------------------------
__device__ __forceinline__ uint32_t smem_u32(const void* p) {
    uint32_t a;
    asm("{ .reg .u64 t; cvta.to.shared.u64 t, %1; cvt.u32.u64 %0, t; }" : "=r"(a) : "l"(p));
    return a;
}
__device__ __forceinline__ float fast_exp2(float x) {
    float y;
    asm("ex2.approx.f32 %0, %1;" : "=f"(y) : "f"(x));
    return y;
}
#define LDSM_X4(r0, r1, r2, r3, addr)                                              \
    asm volatile("ldmatrix.sync.aligned.m8n8.x4.shared.b16 {%0,%1,%2,%3}, [%4];"   \
                 : "=r"(r0), "=r"(r1), "=r"(r2), "=r"(r3) : "r"(addr))
#define LDSM_X4_T(r0, r1, r2, r3, addr)                                            \
    asm volatile("ldmatrix.sync.aligned.m8n8.x4.trans.shared.b16 {%0,%1,%2,%3}, [%4];" \
                 : "=r"(r0), "=r"(r1), "=r"(r2), "=r"(r3) : "r"(addr))
#define MMA_F16(d, a, b)                                                           \
    asm volatile("mma.sync.aligned.m16n8k16.row.col.f32.f16.f16.f32 "              \
                 "{%0,%1,%2,%3}, {%4,%5,%6,%7}, {%8,%9}, {%0,%1,%2,%3};"           \
                 : "+f"((d)[0]), "+f"((d)[1]), "+f"((d)[2]), "+f"((d)[3])          \
                 : "r"((a)[0]), "r"((a)[1]), "r"((a)[2]), "r"((a)[3]),             \
                   "r"((b)[0]), "r"((b)[1]))
#define CP_ASYNC16(dst, src)                                                       \
    asm volatile("cp.async.cg.shared.global [%0], [%1], 16;" :: "r"(dst), "l"(src))
#define CP_COMMIT() asm volatile("cp.async.commit_group;" ::: "memory")
#define CP_WAIT(n) asm volatile("cp.async.wait_group %0;" :: "n"(n) : "memory")

// ---------------------------------------------------------------------------
// scratch (device globals; no runtime alloc)
// ---------------------------------------------------------------------------
#define NW_TOTAL 41943040
#define OFF_WQ 0
#define OFF_WK 16777216
#define OFF_WV 20971520
#define OFF_WO 25165824

__device__ __half g_ha[(size_t)L * HID];      // rmsnorm out, single fp16
__device__ __half g_w[(size_t)NW_TOTAL];      // all weights, single fp16
__device__ __half g_aa[(size_t)L * HID];      // attn out, single fp16
__device__ __half g_qh[(size_t)L * HID];      // roped+scaled Q, single fp16
__device__ __half g_kh[(size_t)L * NKV * HD]; // roped K, single fp16
__device__ __half g_vb[(size_t)L * NKV * HD]; // V, single fp16
__device__ float g_q[(size_t)L * HID];
__device__ float g_k[(size_t)L * NKV * HD];
__device__ float g_v[(size_t)L * NKV * HD];

__device__ __forceinline__ uint32_t pack_f16(float lo, float hi) {
    __half2 t = __floats2half2_rn(lo, hi);  // .x = lo bits [15:0]
    return *(uint32_t*)&t;
}

// ---------------------------------------------------------------------------
// cache copy — rows [L, MAXP) only (rope fully writes rows [0, L))
// ---------------------------------------------------------------------------
__global__ void copy_caches_kernel(const float4* __restrict__ kin,
                                   const float4* __restrict__ vin,
                                   float4* __restrict__ kout,
                                   float4* __restrict__ vout) {
    int idx = blockIdx.x * 256 + threadIdx.x;
    const int n4 = (MAXP - L) * NKV * HD / 4;
    const int off = L * NKV * HD / 4;
    if (idx < n4) kout[off + idx] = kin[off + idx];
    else vout[off + idx - n4] = vin[off + idx - n4];
}

// ---------------------------------------------------------------------------
// fused weight convert: fp32 -> single fp16 (all 4 weights, one launch)
// ---------------------------------------------------------------------------
__global__ void convert_all_kernel(const float4* __restrict__ wq,
                                   const float4* __restrict__ wk,
                                   const float4* __restrict__ wv,
                                   const float4* __restrict__ wo,
                                   __half* __restrict__ w) {
    int i = blockIdx.x * 256 + threadIdx.x;  // [0, NW_TOTAL/4)
    const float4* src;
    int base;
    if (i < OFF_WK / 4) { src = wq; base = 0; }
    else if (i < OFF_WV / 4) { src = wk; base = OFF_WK / 4; }
    else if (i < OFF_WO / 4) { src = wv; base = OFF_WV / 4; }
    else { src = wo; base = OFF_WO / 4; }
    float4 v = src[i - base];
    __half2* hp = (__half2*)(w + (size_t)i * 4);
    hp[0] = __floats2half2_rn(v.x, v.y);
    hp[1] = __floats2half2_rn(v.z, v.w);
}

// ---------------------------------------------------------------------------
// RMSNorm -> single fp16
// ---------------------------------------------------------------------------
__global__ void __launch_bounds__(256) rmsnorm_kernel(const float* __restrict__ x,
                                                      const float* __restrict__ w) {
    int row = blockIdx.x;
    const float* xr = x + (size_t)row * HID;
    int t = threadIdx.x;
    float vals[16];
    float local = 0.f;
#pragma unroll
    for (int i = 0; i < 16; ++i) {
        float v = xr[t + i * 256];
        vals[i] = v;
        local += v * v;
    }
    __shared__ float red[8];
#pragma unroll
    for (int o = 16; o; o >>= 1) local += __shfl_xor_sync(0xffffffffu, local, o);
    if ((t & 31) == 0) red[t >> 5] = local;
    __syncthreads();
    if (t < 8) {
        float v = red[t];
#pragma unroll
        for (int o = 4; o; o >>= 1) v += __shfl_xor_sync(0xffu, v, o);
        if (t == 0) red[0] = v;
    }
    __syncthreads();
    float rms = rsqrtf(red[0] / (float)HID + 1e-5f);
    size_t base = (size_t)row * HID;
#pragma unroll
    for (int i = 0; i < 16; ++i) {
        float y = vals[i] * rms * w[t + i * 256];
        g_ha[base + t + i * 256] = __float2half_rn(y);
    }
}

// ---------------------------------------------------------------------------
// fp16 single-term GEMM: C = A B^T (+res). A, B single fp16.
// CTA 128x128, 256 threads (8 warps 2x4), warp tile 64x32, K-chunk 64,
// 2-stage cp.async, 2 CTAs/SM (72KB smem, ~110 regs) — co-resident CTAs
// cover each other's sync/epilogue bubbles and smooth wave tails.
// MODE 1: fused QKV (N=6144; route q/k/v).  MODE 2: +res.
// ---------------------------------------------------------------------------
#define GSTRIDE 144
#define ATILE 18432            // 128 * 144
#define BOFF  18432
#define GSTAGE 36864           // ATILE + BTILE(128*144)
#define GEMM_SMEM (2 * GSTAGE) // 73728

template <int MODE>
__global__ void __launch_bounds__(256, 2) mma_gemm_kernel(
    const __half* __restrict__ A, const __half* __restrict__ B,
    float* __restrict__ C, float* __restrict__ Ck, float* __restrict__ Cvv,
    int N, const float* __restrict__ res) {
    extern __shared__ char sm[];
    const uint32_t sb = smem_u32(sm);
    const int tid = threadIdx.x;
    const int lane = tid & 31, w = tid >> 5;
    const int wm = w >> 2, wn = w & 3;          // 2 x 4 warps, warp tile 64x32
    const int bm = blockIdx.y * 128, bn = blockIdx.x * 128;

    float acc[4][4][4];
#pragma unroll
    for (int a = 0; a < 4; ++a)
#pragma unroll
        for (int b = 0; b < 4; ++b)
#pragma unroll
            for (int c = 0; c < 4; ++c) acc[a][b][c] = 0.f;

    auto issue = [&](int c, int s) {
#pragma unroll
        for (int j = 0; j < 4; ++j) {            // A: 1024 cp16
            const int local = tid + j * 256;
            const int row = local >> 3;
            const int seg = local & 7;
            const void* g = A + (size_t)(bm + row) * HID + c * 64 + seg * 8;
            uint32_t dst = sb + s * GSTAGE + row * GSTRIDE + seg * 16;
            CP_ASYNC16(dst, g);
        }
#pragma unroll
        for (int j = 0; j < 4; ++j) {            // B: 1024 cp16
            const int local = tid + j * 256;
            const int row = local >> 3;
            const int seg = local & 7;
            const void* g = B + (size_t)(bn + row) * HID + c * 64 + seg * 8;
            uint32_t dst = sb + s * GSTAGE + BOFF + row * GSTRIDE + seg * 16;
            CP_ASYNC16(dst, g);
        }
    };

    auto compute = [&](int s) {
        const uint32_t base = sb + s * GSTAGE;
        const int rsel = lane & 15;
        const int csel = (lane >> 4) << 4;
#pragma unroll
        for (int ks = 0; ks < 4; ++ks) {
            uint32_t a[4][4];
#pragma unroll
            for (int mt = 0; mt < 4; ++mt) {
                uint32_t ad = base + (wm * 64 + mt * 16 + rsel) * GSTRIDE + ks * 32 + csel;
                LDSM_X4(a[mt][0], a[mt][1], a[mt][2], a[mt][3], ad);
            }
            uint32_t b[4][2];
#pragma unroll
            for (int g = 0; g < 2; ++g) {
                uint32_t bd = base + BOFF + (wn * 32 + g * 16 + rsel) * GSTRIDE + ks * 32 + csel;
                uint32_t t0, t1, t2, t3;
                LDSM_X4(t0, t1, t2, t3, bd);
                b[2 * g][0] = t0; b[2 * g][1] = t2;
                b[2 * g + 1][0] = t1; b[2 * g + 1][1] = t3;
            }
#pragma unroll
            for (int nt = 0; nt < 4; ++nt)
#pragma unroll
                for (int mt = 0; mt < 4; ++mt)
                    MMA_F16(acc[mt][nt], a[mt], b[nt]);
        }
    };

    issue(0, 0); CP_COMMIT();
    issue(1, 1); CP_COMMIT();
#pragma unroll 1
    for (int c = 0; c < 64; ++c) {
        if (c + 1 < 64) { CP_WAIT(1); } else { CP_WAIT(0); }
        __syncthreads();
        compute(c & 1);
        if (c + 2 < 64) {
            __syncthreads();
            issue(c + 2, c & 1);
            CP_COMMIT();
        }
    }

    // epilogue: route output
    float* Cout = C;
    int ncols = N, bnl = bn;
    if (MODE == 1) {
        if (bn < 4096) { Cout = C; ncols = 4096; bnl = bn; }
        else if (bn < 5120) { Cout = Ck; ncols = 1024; bnl = bn - 4096; }
        else { Cout = Cvv; ncols = 1024; bnl = bn - 5120; }
    }
#pragma unroll
    for (int mt = 0; mt < 4; ++mt)
#pragma unroll
        for (int nt = 0; nt < 4; ++nt) {
            int row = bm + wm * 64 + mt * 16 + (lane >> 2);
            int col = bnl + wn * 32 + nt * 8 + ((lane & 3) << 1);
            size_t o0 = (size_t)row * ncols + col;
            size_t o1 = (size_t)(row + 8) * ncols + col;
            float2 v0 = make_float2(acc[mt][nt][0], acc[mt][nt][1]);
            float2 v1 = make_float2(acc[mt][nt][2], acc[mt][nt][3]);
            if (MODE == 2) {
                float2 r0 = *(const float2*)&res[o0];
                float2 r1 = *(const float2*)&res[o1];
                v0.x += r0.x; v0.y += r0.y;
                v1.x += r1.x; v1.y += r1.y;
            }
            *(float2*)&Cout[o0] = v0;
            *(float2*)&Cout[o1] = v1;
        }
}

// ---------------------------------------------------------------------------
// fused RoPE: Q (scaled fp16) + K (fp16 + fp32 cache) + V passthrough
// ---------------------------------------------------------------------------
#define QTOTAL (L * NH * 64)
#define KVTOTAL (L * NKV * 64)
__global__ void rope_all_kernel(const float* __restrict__ cosb, const float* __restrict__ sinb,
                                float* __restrict__ kc_out, float* __restrict__ vc_out) {
    const float QS = 0.08838834764831845f * 1.4426950408889634f;
    int idx = blockIdx.x * 256 + threadIdx.x;
    if (idx < QTOTAL) {
        int d = idx & 63;
        int h = (idx >> 6) & (NH - 1);
        int i = idx >> 11;
        const float* qp = g_q + (size_t)i * HID + h * HD;
        float c0 = cosb[i * HD + d], s0 = sinb[i * HD + d];
        float c1 = cosb[i * HD + d + 64], s1 = sinb[i * HD + d + 64];
        float q0 = qp[d], q1 = qp[d + 64];
        size_t base = (size_t)i * HID + h * HD;
        g_qh[base + d] = __float2half_rn((q0 * c0 - q1 * s0) * QS);
        g_qh[base + d + 64] = __float2half_rn((q1 * c1 + q0 * s1) * QS);
    } else {
        idx -= QTOTAL;
        int d = idx & 63;
        int h = (idx >> 6) & (NKV - 1);
        int i = idx >> 9;
        size_t base = (size_t)i * (NKV * HD) + h * HD;
        float c0 = cosb[i * HD + d], s0 = sinb[i * HD + d];
        float c1 = cosb[i * HD + d + 64], s1 = sinb[i * HD + d + 64];
        float k0 = g_k[base + d], k1 = g_k[base + d + 64];
        float k0n = k0 * c0 - k1 * s0;
        float k1n = k1 * c1 + k0 * s1;
        kc_out[base + d] = k0n;
        kc_out[base + d + 64] = k1n;
        g_kh[base + d] = __float2half_rn(k0n);
        g_kh[base + d + 64] = __float2half_rn(k1n);
        float v0 = g_v[base + d], v1 = g_v[base + d + 64];
        vc_out[base + d] = v0;
        vc_out[base + d + 64] = v1;
        g_vb[base + d] = __float2half_rn(v0);
        g_vb[base + d + 64] = __float2half_rn(v1);
    }
}

// ---------------------------------------------------------------------------
// Flash attention via fp16 mma: BM=128 (8 warps x m16), BN=64, HD=128.
// Double-buffered K/V with cross-iteration prefetch; 2 CTAs/SM.
// ---------------------------------------------------------------------------
#define FSTRIDE 272
#define FQ 0
#define FK0 34816
#define FK1 52224
#define FV0 69632
#define FV1 87040
#define FLASH_SMEM 104448

__global__ void __launch_bounds__(256, 2) flash_kernel() {
    extern __shared__ char sm[];
    const uint32_t sb = smem_u32(sm);
    const int tid = threadIdx.x;
    const int lane = tid & 31, w = tid >> 5;
    const int qt = gridDim.x - 1 - blockIdx.x;  // heavy tiles first
    const int head = blockIdx.y;
    const int kvh = head >> 2;
    const int rsel = lane & 15;
    const int csel = (lane >> 4) << 4;

    auto issue_kv = [&](int kt, int s) {
        const uint32_t kb = sb + (s ? FK1 : FK0);
        const uint32_t vb = sb + (s ? FV1 : FV0);
#pragma unroll
        for (int j = 0; j < 4; ++j) {
            const int local = tid + j * 256;
            const int row = local >> 4;
            const int seg = local & 15;
            size_t goff = (size_t)(kt * 64 + row) * (NKV * HD) + kvh * HD + seg * 8;
            CP_ASYNC16(kb + row * FSTRIDE + seg * 16, g_kh + goff);
        }
#pragma unroll
        for (int j = 0; j < 4; ++j) {
            const int local = tid + j * 256;
            const int row = local >> 4;
            const int seg = local & 15;
            size_t goff = (size_t)(kt * 64 + row) * (NKV * HD) + kvh * HD + seg * 8;
            CP_ASYNC16(vb + row * FSTRIDE + seg * 16, g_vb + goff);
        }
    };

#pragma unroll
    for (int j = 0; j < 8; ++j) {
        const int local = tid + j * 256;
        const int row = local >> 4;
        const int seg = local & 15;
        const void* g = g_qh + (size_t)(qt * 128 + row) * HID + head * HD + seg * 8;
        CP_ASYNC16(sb + FQ + row * FSTRIDE + seg * 16, g);
    }
    issue_kv(0, 0);
    CP_COMMIT();

    float o_[16][4];
#pragma unroll
    for (int n = 0; n < 16; ++n)
#pragma unroll
        for (int c = 0; c < 4; ++c) o_[n][c] = 0.f;
    float m_[2] = {-1e30f, -1e30f};
    float l_[2] = {0.f, 0.f};

    const int kt_end = 2 * qt + 2;
#pragma unroll 1
    for (int kt = 0; kt < kt_end; ++kt) {
        const int s = kt & 1;
        CP_WAIT(0);
        __syncthreads();
        if (kt + 1 < kt_end) {
            issue_kv(kt + 1, s ^ 1);
            CP_COMMIT();
        }
        const uint32_t kb = sb + (s ? FK1 : FK0);
        const uint32_t vb = sb + (s ? FV1 : FV0);

        float sc[8][4];
#pragma unroll
        for (int n = 0; n < 8; ++n)
#pragma unroll
            for (int c = 0; c < 4; ++c) sc[n][c] = 0.f;
#pragma unroll
        for (int ks = 0; ks < 8; ++ks) {
            uint32_t a[4];
            uint32_t aaddr = sb + FQ + (w * 16 + rsel) * FSTRIDE + ks * 32 + csel;
            LDSM_X4(a[0], a[1], a[2], a[3], aaddr);
#pragma unroll
            for (int half = 0; half < 2; ++half) {
                uint32_t b[4][2];
#pragma unroll
                for (int g = 0; g < 2; ++g) {
                    uint32_t bd = kb + ((half * 2 + g) * 16 + rsel) * FSTRIDE + ks * 32 + csel;
                    uint32_t t0, t1, t2, t3;
                    LDSM_X4(t0, t1, t2, t3, bd);
                    b[2 * g][0] = t0; b[2 * g][1] = t2;
                    b[2 * g + 1][0] = t1; b[2 * g + 1][1] = t3;
                }
#pragma unroll
                for (int n = 0; n < 4; ++n) MMA_F16(sc[half * 4 + n], a, b[n]);
            }
        }

        if (kt >= 2 * qt) {
            const int r0g = qt * 128 + w * 16 + (lane >> 2);
#pragma unroll
            for (int j = 0; j < 8; ++j) {
                int cb = kt * 64 + j * 8 + ((lane & 3) << 1);
                if (cb > r0g) sc[j][0] = -1e30f;
                if (cb + 1 > r0g) sc[j][1] = -1e30f;
                if (cb > r0g + 8) sc[j][2] = -1e30f;
                if (cb + 1 > r0g + 8) sc[j][3] = -1e30f;
            }
        }

#pragma unroll
        for (int i = 0; i < 2; ++i) {
            float mt_ = -1e30f;
#pragma unroll
            for (int j = 0; j < 8; ++j)
                mt_ = fmaxf(mt_, fmaxf(sc[j][2 * i], sc[j][2 * i + 1]));
            mt_ = fmaxf(mt_, __shfl_xor_sync(0xffffffffu, mt_, 1));
            mt_ = fmaxf(mt_, __shfl_xor_sync(0xffffffffu, mt_, 2));
            float mn = fmaxf(m_[i], mt_);
            float corr = fast_exp2(m_[i] - mn);
            m_[i] = mn;
            float rs = 0.f;
#pragma unroll
            for (int j = 0; j < 8; ++j) {
                float p0 = fast_exp2(sc[j][2 * i] - mn);
                float p1 = fast_exp2(sc[j][2 * i + 1] - mn);
                sc[j][2 * i] = p0;
                sc[j][2 * i + 1] = p1;
                rs += p0 + p1;
            }
            rs += __shfl_xor_sync(0xffffffffu, rs, 1);
            rs += __shfl_xor_sync(0xffffffffu, rs, 2);
            l_[i] = l_[i] * corr + rs;
#pragma unroll
            for (int n = 0; n < 16; ++n) {
                o_[n][2 * i] *= corr;
                o_[n][2 * i + 1] *= corr;
            }
        }

        uint32_t pa[4][4];
#pragma unroll
        for (int t = 0; t < 4; ++t) {
            pa[t][0] = pack_f16(sc[2 * t][0], sc[2 * t][1]);
            pa[t][1] = pack_f16(sc[2 * t][2], sc[2 * t][3]);
            pa[t][2] = pack_f16(sc[2 * t + 1][0], sc[2 * t + 1][1]);
            pa[t][3] = pack_f16(sc[2 * t + 1][2], sc[2 * t + 1][3]);
        }

#pragma unroll
        for (int t = 0; t < 4; ++t) {
#pragma unroll
            for (int g = 0; g < 8; ++g) {
                uint32_t vaddr = vb + (t * 16 + rsel) * FSTRIDE +
                                 (g * 16 + ((lane >> 4) << 3)) * 2;
                uint32_t t0, t1, t2, t3;
                LDSM_X4_T(t0, t1, t2, t3, vaddr);
                uint32_t b0[2] = {t0, t1}, b1[2] = {t2, t3};
                MMA_F16(o_[2 * g], pa[t], b0);
                MMA_F16(o_[2 * g + 1], pa[t], b1);
            }
        }
    }

    const float inv0 = 1.f / l_[0];
    const float inv1 = 1.f / l_[1];
    const int r0g = qt * 128 + w * 16 + (lane >> 2);
#pragma unroll
    for (int nt = 0; nt < 16; ++nt) {
        int col = head * HD + nt * 8 + ((lane & 3) << 1);
        size_t o0 = (size_t)r0g * HID + col;
        size_t o1 = o0 + (size_t)8 * HID;
        *(__half2*)(g_aa + o0) = __floats2half2_rn(o_[nt][0] * inv0, o_[nt][1] * inv0);
        *(__half2*)(g_aa + o1) = __floats2half2_rn(o_[nt][2] * inv1, o_[nt][3] * inv1);
    }
}

// ---------------------------------------------------------------------------
// launch
// ---------------------------------------------------------------------------
extern "C" void kernel_launch(void* const* d_in, const int* in_sizes, int n_in,
                              void* d_out, int out_size) {
    const float* x = (const float*)d_in[0];
    const float* cosb = (const float*)d_in[1];
    const float* sinb = (const float*)d_in[2];
    // d_in[3] position_ids (arange; not dereferenced), d_in[4] seq_len
    const float* kc_in = (const float*)d_in[5];
    const float* vc_in = (const float*)d_in[6];
    const float* lnw = (const float*)d_in[7];
    const float* Wq = (const float*)d_in[8];
    const float* Wk = (const float*)d_in[9];
    const float* Wv = (const float*)d_in[10];
    const float* Wo = (const float*)d_in[11];

    float* out = (float*)d_out;
    float* kc_out = out + (size_t)L * HID;
    float* vc_out = kc_out + (size_t)MAXP * NKV * HD;

    __half *pHa, *pW, *pAa;
    float *pQ, *pK, *pV;
    cudaGetSymbolAddress((void**)&pHa, g_ha);
    cudaGetSymbolAddress((void**)&pW, g_w);
    cudaGetSymbolAddress((void**)&pAa, g_aa);
    cudaGetSymbolAddress((void**)&pQ, g_q);
    cudaGetSymbolAddress((void**)&pK, g_k);
    cudaGetSymbolAddress((void**)&pV, g_v);

    copy_caches_kernel<<<(2 * (MAXP - L) * NKV * HD / 4) / 256, 256>>>(
        (const float4*)kc_in, (const float4*)vc_in, (float4*)kc_out, (float4*)vc_out);

    convert_all_kernel<<<(NW_TOTAL / 4) / 256, 256>>>(
        (const float4*)Wq, (const float4*)Wk, (const float4*)Wv, (const float4*)Wo, pW);

    rmsnorm_kernel<<<L, 256>>>(x, lnw);

    cudaFuncSetAttribute((const void*)mma_gemm_kernel<1>,
                         cudaFuncAttributeMaxDynamicSharedMemorySize, GEMM_SMEM);
    cudaFuncSetAttribute((const void*)mma_gemm_kernel<2>,
                         cudaFuncAttributeMaxDynamicSharedMemorySize, GEMM_SMEM);

    // fused Q+K+V projection: N = 6144, grid (48, 16) = 768 CTAs, 2/SM
    mma_gemm_kernel<1><<<dim3(6144 / 128, L / 128), 256, GEMM_SMEM>>>(
        pHa, pW, pQ, pK, pV, 6144, nullptr);

    rope_all_kernel<<<(QTOTAL + KVTOTAL) / 256, 256>>>(cosb, sinb, kc_out, vc_out);

    cudaFuncSetAttribute(flash_kernel, cudaFuncAttributeMaxDynamicSharedMemorySize, FLASH_SMEM);
    flash_kernel<<<dim3(L / 128, NH), 256, FLASH_SMEM>>>();

    // O projection with residual: grid (32, 16) = 512 CTAs, 2/SM
    mma_gemm_kernel<2><<<dim3(HID / 128, L / 128), 256, GEMM_SMEM>>>(
        pAa, pW + OFF_WO, out, nullptr, nullptr, HID, x);
}